// round 9
// baseline (speedup 1.0000x reference)
#include <cuda_runtime.h>
#include <cstdint>

#define C 64
#define MAXN 50000
#define MAXE 800000

// ---------------- device scratch (static: no allocation allowed) ----------------
__device__ float g_v[MAXN * C];
__device__ float g_Q1[MAXN * C];
__device__ float g_K1[MAXN * C];
__device__ float g_P1[MAXN * C];
__device__ float g_num[MAXN * C];
__device__ float g_den[MAXN * C];
__device__ float g_Mq_t[C * C];
__device__ float g_Mk_t[C * C];
__device__ float g_Win_t[C * C];
__device__ float g_Wlin_t[C * C];
__device__ float g_w2a_t[C * C];
__device__ float g_w2p_t[C * C];
__device__ float g_Wout_t[C * C];
__device__ float g_delta0[C];
__device__ float g_fWin[4096];
__device__ float g_fWlin[4096];
__device__ float g_fMq[4096];
__device__ float g_fMk[4096];
__device__ float g_fW2a[4096];
__device__ float g_fW2p[4096];
__device__ float g_fWout[4096];

__device__ __forceinline__ unsigned f2tf32(float f) {
    unsigned r;
    asm("cvt.rna.tf32.f32 %0, %1;" : "=r"(r) : "f"(f));
    return r;
}

#define MMA_TF32(d, a, b0, b1)                                               \
    asm volatile("mma.sync.aligned.m16n8k8.row.col.f32.tf32.tf32.f32 "       \
                 "{%0,%1,%2,%3}, {%4,%5,%6,%7}, {%8,%9}, {%0,%1,%2,%3};"     \
                 : "+f"(d[0]), "+f"(d[1]), "+f"(d[2]), "+f"(d[3])            \
                 : "r"(a[0]), "r"(a[1]), "r"(a[2]), "r"(a[3]),               \
                   "r"(b0), "r"(b1))

#define RED_V4(ptr, v)                                                       \
    asm volatile("red.global.add.v4.f32 [%0], {%1,%2,%3,%4};"                \
                 :: "l"(ptr), "f"((v).x), "f"((v).y), "f"((v).z), "f"((v).w) \
                 : "memory")

// ---------------- K0: weight prep ------------------------------------------------
__global__ void prep_kernel(const float* __restrict__ att_w1,
                            const float* __restrict__ W_dst,
                            const float* __restrict__ W_src,
                            const float* __restrict__ W_in,
                            const float* __restrict__ W_lin,
                            const float* __restrict__ att_w2,
                            const float* __restrict__ pos_w2,
                            const float* __restrict__ W_out,
                            const float* __restrict__ pos_b1,
                            const float* __restrict__ pos_b2)
{
    __shared__ float s_a[C * C];
    __shared__ float s_d[C * C];
    __shared__ float s_s[C * C];
    int tid = threadIdx.x;
    for (int t = tid; t < C * C; t += blockDim.x) {
        s_a[t] = att_w1[t];
        s_d[t] = W_dst[t];
        s_s[t] = W_src[t];
    }
    __syncthreads();
    for (int idx = tid; idx < C * C; idx += blockDim.x) {
        int t = idx >> 6, j = idx & 63;
        float aq = 0.f, ak = 0.f;
        #pragma unroll 8
        for (int u = 0; u < C; u++) {
            float a = s_a[t * C + u];
            aq = fmaf(a, s_d[u * C + j], aq);
            ak = fmaf(a, s_s[u * C + j], ak);
        }
        g_Mq_t[j * C + t] = aq;
        g_Mk_t[j * C + t] = ak;
    }
    for (int idx = tid; idx < C * C; idx += blockDim.x) {
        int cc = idx >> 6, j = idx & 63;
        g_Win_t[j * C + cc]  = W_in[idx];
        g_Wlin_t[j * C + cc] = W_lin[idx];
        g_w2a_t[j * C + cc]  = att_w2[idx];
        g_w2p_t[j * C + cc]  = pos_w2[idx];
        g_Wout_t[j * C + cc] = W_out[idx];
    }
    if (tid < C) {
        float acc = pos_b2[tid];
        #pragma unroll 8
        for (int j = 0; j < C; j++)
            acc = fmaf(fmaxf(pos_b1[j], 0.f), pos_w2[tid * C + j], acc);
        g_delta0[tid] = fmaxf(acc, 0.f);
    }
    __syncthreads();
    for (int t = tid; t < 2048; t += blockDim.x) {
        int kt   = t >> 8;
        int nt   = (t >> 5) & 7;
        int lane = t & 31;
        int kr = kt * 8 + (lane & 3);
        int nc = nt * 8 + (lane >> 2);
        int lo = kr * 64 + nc, hi = (kr + 4) * 64 + nc;
        ((float2*)g_fWin)[t]  = make_float2(__uint_as_float(f2tf32(g_Win_t[lo])),
                                            __uint_as_float(f2tf32(g_Win_t[hi])));
        ((float2*)g_fWlin)[t] = make_float2(__uint_as_float(f2tf32(g_Wlin_t[lo])),
                                            __uint_as_float(f2tf32(g_Wlin_t[hi])));
        ((float2*)g_fMq)[t]   = make_float2(__uint_as_float(f2tf32(g_Mq_t[lo])),
                                            __uint_as_float(f2tf32(g_Mq_t[hi])));
        ((float2*)g_fMk)[t]   = make_float2(__uint_as_float(f2tf32(g_Mk_t[lo])),
                                            __uint_as_float(f2tf32(g_Mk_t[hi])));
        ((float2*)g_fW2a)[t]  = make_float2(__uint_as_float(f2tf32(g_w2a_t[lo])),
                                            __uint_as_float(f2tf32(g_w2a_t[hi])));
        ((float2*)g_fW2p)[t]  = make_float2(__uint_as_float(f2tf32(g_w2p_t[lo])),
                                            __uint_as_float(f2tf32(g_w2p_t[hi])));
        ((float2*)g_fWout)[t] = make_float2(__uint_as_float(f2tf32(g_Wout_t[lo])),
                                            __uint_as_float(f2tf32(g_Wout_t[hi])));
    }
}

// ---------------- dummy (instrumentation spacer so ncu window hits edge_kernel) --
__global__ void spacer_kernel() {}

// ---------------- K1: node kernel — 5 fused tf32 GEMMs over 64-node tiles -------
__global__ void __launch_bounds__(256)
node_kernel(const float* __restrict__ x,
            const float* __restrict__ pos,
            const float* __restrict__ pos_w1,
            const float* __restrict__ b_in,
            const float* __restrict__ att_b1,
            const float* __restrict__ att_b2,
            int n)
{
    extern __shared__ float sm[];
    float* xs = sm;
    float* hs = sm + 4352;
    float* vs = sm + 8704;
    int tid  = threadIdx.x;
    int lane = tid & 31;
    int wid  = tid >> 5;
    int base = blockIdx.x * 64;

    for (int t = tid; t < 1024; t += 256) {
        int row = t >> 4;
        int col = (t & 15) * 4;
        int node = base + row;
        float4 v4 = make_float4(0.f, 0.f, 0.f, 0.f);
        if (node < n) v4 = *(const float4*)(x + (size_t)node * C + col);
        float4 r;
        r.x = __uint_as_float(f2tf32(v4.x));
        r.y = __uint_as_float(f2tf32(v4.y));
        r.z = __uint_as_float(f2tf32(v4.z));
        r.w = __uint_as_float(f2tf32(v4.w));
        *(float4*)(xs + row * 68 + col) = r;
    }
    {
        int row = tid >> 2;
        int node = base + row;
        if (node < n) {
            float px = pos[(size_t)node * 3 + 0];
            float py = pos[(size_t)node * 3 + 1];
            float pz = pos[(size_t)node * 3 + 2];
            int c0 = (tid & 3) * 16;
            #pragma unroll
            for (int c = c0; c < c0 + 16; c++) {
                g_P1[(size_t)node * C + c] =
                    px * pos_w1[c * 3 + 0] + py * pos_w1[c * 3 + 1] + pz * pos_w1[c * 3 + 2];
            }
        }
    }
    __syncthreads();

    int r0 = (wid & 3) * 16;
    int nh = wid >> 2;
    int n0 = nh * 32;
    int rA = lane >> 2;
    int cb = 2 * (lane & 3);
    int rowg0 = base + r0 + rA;
    int rowg1 = rowg0 + 8;
    bool ok0 = rowg0 < n, ok1 = rowg1 < n;

    {
        float acc[4][4];
        #pragma unroll
        for (int nt = 0; nt < 4; nt++) {
            int col = n0 + nt * 8 + cb;
            float b0 = b_in[col], b1 = b_in[col + 1];
            acc[nt][0] = b0; acc[nt][1] = b1; acc[nt][2] = b0; acc[nt][3] = b1;
        }
        #pragma unroll
        for (int kt = 0; kt < 8; kt++) {
            int cA = kt * 8 + (lane & 3);
            unsigned a[4];
            a[0] = __float_as_uint(xs[(r0 + rA) * 68 + cA]);
            a[1] = __float_as_uint(xs[(r0 + 8 + rA) * 68 + cA]);
            a[2] = __float_as_uint(xs[(r0 + rA) * 68 + cA + 4]);
            a[3] = __float_as_uint(xs[(r0 + 8 + rA) * 68 + cA + 4]);
            #pragma unroll
            for (int nt = 0; nt < 4; nt++) {
                float2 b = ((const float2*)g_fWin)[(kt * 8 + nh * 4 + nt) * 32 + lane];
                MMA_TF32(acc[nt], a, __float_as_uint(b.x), __float_as_uint(b.y));
            }
        }
        #pragma unroll
        for (int nt = 0; nt < 4; nt++) {
            int col = n0 + nt * 8 + cb;
            hs[(r0 + rA) * 68 + col]       = __uint_as_float(f2tf32(fmaxf(acc[nt][0], 0.f)));
            hs[(r0 + rA) * 68 + col + 1]   = __uint_as_float(f2tf32(fmaxf(acc[nt][1], 0.f)));
            hs[(r0 + 8 + rA) * 68 + col]     = __uint_as_float(f2tf32(fmaxf(acc[nt][2], 0.f)));
            hs[(r0 + 8 + rA) * 68 + col + 1] = __uint_as_float(f2tf32(fmaxf(acc[nt][3], 0.f)));
        }
    }
    __syncthreads();

    {
        float acc[4][4];
        #pragma unroll
        for (int nt = 0; nt < 4; nt++)
            #pragma unroll
            for (int q = 0; q < 4; q++) acc[nt][q] = 0.f;
        #pragma unroll
        for (int kt = 0; kt < 8; kt++) {
            int cA = kt * 8 + (lane & 3);
            unsigned a[4];
            a[0] = __float_as_uint(hs[(r0 + rA) * 68 + cA]);
            a[1] = __float_as_uint(hs[(r0 + 8 + rA) * 68 + cA]);
            a[2] = __float_as_uint(hs[(r0 + rA) * 68 + cA + 4]);
            a[3] = __float_as_uint(hs[(r0 + 8 + rA) * 68 + cA + 4]);
            #pragma unroll
            for (int nt = 0; nt < 4; nt++) {
                float2 b = ((const float2*)g_fWlin)[(kt * 8 + nh * 4 + nt) * 32 + lane];
                MMA_TF32(acc[nt], a, __float_as_uint(b.x), __float_as_uint(b.y));
            }
        }
        #pragma unroll
        for (int nt = 0; nt < 4; nt++) {
            int col = n0 + nt * 8 + cb;
            vs[(r0 + rA) * 68 + col]         = acc[nt][0];
            vs[(r0 + rA) * 68 + col + 1]     = acc[nt][1];
            vs[(r0 + 8 + rA) * 68 + col]     = acc[nt][2];
            vs[(r0 + 8 + rA) * 68 + col + 1] = acc[nt][3];
            if (ok0) *(float2*)(g_v + (size_t)rowg0 * C + col) = make_float2(acc[nt][0], acc[nt][1]);
            if (ok1) *(float2*)(g_v + (size_t)rowg1 * C + col) = make_float2(acc[nt][2], acc[nt][3]);
        }
    }
    {
        float aq[4][4], ak[4][4];
        #pragma unroll
        for (int nt = 0; nt < 4; nt++)
            #pragma unroll
            for (int q = 0; q < 4; q++) { aq[nt][q] = 0.f; ak[nt][q] = 0.f; }
        #pragma unroll
        for (int kt = 0; kt < 8; kt++) {
            int cA = kt * 8 + (lane & 3);
            unsigned a[4];
            a[0] = __float_as_uint(hs[(r0 + rA) * 68 + cA]);
            a[1] = __float_as_uint(hs[(r0 + 8 + rA) * 68 + cA]);
            a[2] = __float_as_uint(hs[(r0 + rA) * 68 + cA + 4]);
            a[3] = __float_as_uint(hs[(r0 + 8 + rA) * 68 + cA + 4]);
            #pragma unroll
            for (int nt = 0; nt < 4; nt++) {
                float2 bq = ((const float2*)g_fMq)[(kt * 8 + nh * 4 + nt) * 32 + lane];
                float2 bk = ((const float2*)g_fMk)[(kt * 8 + nh * 4 + nt) * 32 + lane];
                MMA_TF32(aq[nt], a, __float_as_uint(bq.x), __float_as_uint(bq.y));
                MMA_TF32(ak[nt], a, __float_as_uint(bk.x), __float_as_uint(bk.y));
            }
        }
        #pragma unroll
        for (int nt = 0; nt < 4; nt++) {
            int col = n0 + nt * 8 + cb;
            float ba0 = att_b1[col], ba1 = att_b1[col + 1];
            xs[(r0 + rA) * 68 + col]       = __uint_as_float(f2tf32(fmaxf(aq[nt][0] - ak[nt][0] + ba0, 0.f)));
            xs[(r0 + rA) * 68 + col + 1]   = __uint_as_float(f2tf32(fmaxf(aq[nt][1] - ak[nt][1] + ba1, 0.f)));
            xs[(r0 + 8 + rA) * 68 + col]     = __uint_as_float(f2tf32(fmaxf(aq[nt][2] - ak[nt][2] + ba0, 0.f)));
            xs[(r0 + 8 + rA) * 68 + col + 1] = __uint_as_float(f2tf32(fmaxf(aq[nt][3] - ak[nt][3] + ba1, 0.f)));
            if (ok0) {
                *(float2*)(g_Q1 + (size_t)rowg0 * C + col) = make_float2(aq[nt][0], aq[nt][1]);
                *(float2*)(g_K1 + (size_t)rowg0 * C + col) = make_float2(ak[nt][0], ak[nt][1]);
            }
            if (ok1) {
                *(float2*)(g_Q1 + (size_t)rowg1 * C + col) = make_float2(aq[nt][2], aq[nt][3]);
                *(float2*)(g_K1 + (size_t)rowg1 * C + col) = make_float2(ak[nt][2], ak[nt][3]);
            }
        }
    }
    __syncthreads();

    {
        float acc[4][4];
        #pragma unroll
        for (int nt = 0; nt < 4; nt++) {
            int col = n0 + nt * 8 + cb;
            float b0 = att_b2[col], b1 = att_b2[col + 1];
            acc[nt][0] = b0; acc[nt][1] = b1; acc[nt][2] = b0; acc[nt][3] = b1;
        }
        #pragma unroll
        for (int kt = 0; kt < 8; kt++) {
            int cA = kt * 8 + (lane & 3);
            unsigned a[4];
            a[0] = __float_as_uint(xs[(r0 + rA) * 68 + cA]);
            a[1] = __float_as_uint(xs[(r0 + 8 + rA) * 68 + cA]);
            a[2] = __float_as_uint(xs[(r0 + rA) * 68 + cA + 4]);
            a[3] = __float_as_uint(xs[(r0 + 8 + rA) * 68 + cA + 4]);
            #pragma unroll
            for (int nt = 0; nt < 4; nt++) {
                float2 b = ((const float2*)g_fW2a)[(kt * 8 + nh * 4 + nt) * 32 + lane];
                MMA_TF32(acc[nt], a, __float_as_uint(b.x), __float_as_uint(b.y));
            }
        }
        #pragma unroll
        for (int nt = 0; nt < 4; nt++) {
            int col = n0 + nt * 8 + cb;
            float d0 = g_delta0[col], d1 = g_delta0[col + 1];
            float e0 = __expf(fmaxf(acc[nt][0], 0.f));
            float e1 = __expf(fmaxf(acc[nt][1], 0.f));
            float e2 = __expf(fmaxf(acc[nt][2], 0.f));
            float e3 = __expf(fmaxf(acc[nt][3], 0.f));
            if (ok0) {
                float v0 = vs[(r0 + rA) * 68 + col];
                float v1 = vs[(r0 + rA) * 68 + col + 1];
                *(float2*)(g_den + (size_t)rowg0 * C + col) = make_float2(e0, e1);
                *(float2*)(g_num + (size_t)rowg0 * C + col) = make_float2(e0 * (v0 + d0), e1 * (v1 + d1));
            }
            if (ok1) {
                float v2 = vs[(r0 + 8 + rA) * 68 + col];
                float v3 = vs[(r0 + 8 + rA) * 68 + col + 1];
                *(float2*)(g_den + (size_t)rowg1 * C + col) = make_float2(e2, e3);
                *(float2*)(g_num + (size_t)rowg1 * C + col) = make_float2(e2 * (v2 + d0), e3 * (v3 + d1));
            }
        }
    }
}

// ---------------- K2: edge kernel — R5 pipeline, streamed B frags, 3 blocks/SM --
__global__ void __launch_bounds__(256, 3)
edge_kernel(const int* __restrict__ src, const int* __restrict__ dst,
            const float* __restrict__ att_b1, const float* __restrict__ pos_b1,
            const float* __restrict__ att_b2, const float* __restrict__ pos_b2,
            int E)
{
    extern __shared__ float smE[];
    float* hidA = smE;
    float* hidP = smE + 4352;
    float* exA  = smE + 8704;
    float* dlP  = smE + 13056;
    int*   seB  = (int*)(smE + 17408);   // [2][64]
    int*   deB  = seB + 128;

    int tid  = threadIdx.x;
    int lane = tid & 31;
    int wid  = tid >> 5;
    bool isA = (wid < 4);
    int sub  = wid & 3;
    int nhE  = sub & 1;
    int n0b  = nhE * 32;
    int mp   = sub >> 1;
    int r0m  = mp * 16;
    int r1m  = (mp + 2) * 16;

    const float* b2   = isA ? att_b2 : pos_b2;
    const float2* fW2 = isA ? (const float2*)g_fW2a : (const float2*)g_fW2p;
    float* hid = isA ? hidA : hidP;
    float* res = isA ? exA  : dlP;

    float bias0[4], bias1[4];
    #pragma unroll
    for (int nt = 0; nt < 4; nt++) {
        int col = n0b + nt * 8 + 2 * (lane & 3);
        bias0[nt] = b2[col];
        bias1[nt] = b2[col + 1];
    }

    // gather/scatter role: 16-lane group owns col slice js for edges {slot+16k}
    int slot = tid >> 4;
    int js   = (tid & 15) << 2;
    float4 ba1 = *(const float4*)(att_b1 + js);
    float4 bp1 = *(const float4*)(pos_b1 + js);

    int sPrev[4], dPrev[4];
    #pragma unroll
    for (int k = 0; k < 4; k++) dPrev[k] = -1;

    int ntiles = (E + 63) >> 6;

    {
        int base = blockIdx.x << 6;
        if (tid < 64) {
            int e = base + tid;
            seB[tid] = (e < E) ? src[e] : 0;
        } else if (tid < 128) {
            int e = base + tid - 64;
            deB[tid - 64] = (e < E) ? dst[e] : -1;
        }
    }
    __syncthreads();

    int it = 0;
    for (int tile = blockIdx.x; tile < ntiles; tile += gridDim.x, it ^= 1) {
        // ===== PHASE A: scatter(prev) + gather(cur) + idx prefetch(next) =====
        #pragma unroll
        for (int k = 0; k < 4; k++) {
            int d = dPrev[k];
            if (d >= 0) {
                int e = slot + 16 * k;
                float4 ex = *(const float4*)(exA + e * 68 + js);
                float4 dl = *(const float4*)(dlP + e * 68 + js);
                float4 vv = *(const float4*)(g_v + (size_t)sPrev[k] * C + js);
                float4 nv;
                nv.x = ex.x * (vv.x + dl.x);
                nv.y = ex.y * (vv.y + dl.y);
                nv.z = ex.z * (vv.z + dl.z);
                nv.w = ex.w * (vv.w + dl.w);
                RED_V4(g_num + (size_t)d * C + js, nv);
                RED_V4(g_den + (size_t)d * C + js, ex);
            }
        }
        #pragma unroll
        for (int k = 0; k < 4; k++) {
            int e = slot + 16 * k;
            int s = seB[it * 64 + e];
            int d = deB[it * 64 + e];
            sPrev[k] = s;
            dPrev[k] = d;
            int dc = d < 0 ? 0 : d;
            float4 qv = *(const float4*)(g_Q1 + (size_t)dc * C + js);
            float4 kv = *(const float4*)(g_K1 + (size_t)s  * C + js);
            float4 ra;
            ra.x = __uint_as_float(f2tf32(fmaxf(qv.x - kv.x + ba1.x, 0.f)));
            ra.y = __uint_as_float(f2tf32(fmaxf(qv.y - kv.y + ba1.y, 0.f)));
            ra.z = __uint_as_float(f2tf32(fmaxf(qv.z - kv.z + ba1.z, 0.f)));
            ra.w = __uint_as_float(f2tf32(fmaxf(qv.w - kv.w + ba1.w, 0.f)));
            float4 pd = *(const float4*)(g_P1 + (size_t)dc * C + js);
            float4 ps = *(const float4*)(g_P1 + (size_t)s  * C + js);
            float4 rp;
            rp.x = __uint_as_float(f2tf32(fmaxf(pd.x - ps.x + bp1.x, 0.f)));
            rp.y = __uint_as_float(f2tf32(fmaxf(pd.y - ps.y + bp1.y, 0.f)));
            rp.z = __uint_as_float(f2tf32(fmaxf(pd.z - ps.z + bp1.z, 0.f)));
            rp.w = __uint_as_float(f2tf32(fmaxf(pd.w - ps.w + bp1.w, 0.f)));
            if (d < 0) {
                ra = make_float4(0.f, 0.f, 0.f, 0.f);
                rp = ra;
            }
            *(float4*)(hidA + e * 68 + js) = ra;
            *(float4*)(hidP + e * 68 + js) = rp;
        }
        {
            int ntile = tile + gridDim.x;
            if (ntile < ntiles) {
                int base = ntile << 6;
                int ib = (it ^ 1) * 64;
                if (tid < 64) {
                    int e = base + tid;
                    seB[ib + tid] = (e < E) ? src[e] : 0;
                } else if (tid < 128) {
                    int e = base + tid - 64;
                    deB[ib + tid - 64] = (e < E) ? dst[e] : -1;
                }
            }
        }
        __syncthreads();

        // ===== PHASE B: tensor-core MMA (streamed B frags) + epilogue =====
        float acc[2][4][4];
        #pragma unroll
        for (int s2 = 0; s2 < 2; s2++)
            #pragma unroll
            for (int nt = 0; nt < 4; nt++) {
                acc[s2][nt][0] = bias0[nt];
                acc[s2][nt][1] = bias1[nt];
                acc[s2][nt][2] = bias0[nt];
                acc[s2][nt][3] = bias1[nt];
            }
        int rA = lane >> 2;
        #pragma unroll
        for (int kt = 0; kt < 8; kt++) {
            int cA = kt * 8 + (lane & 3);
            unsigned a[2][4];
            a[0][0] = __float_as_uint(hid[(r0m + rA) * 68 + cA]);
            a[0][1] = __float_as_uint(hid[(r0m + 8 + rA) * 68 + cA]);
            a[0][2] = __float_as_uint(hid[(r0m + rA) * 68 + cA + 4]);
            a[0][3] = __float_as_uint(hid[(r0m + 8 + rA) * 68 + cA + 4]);
            a[1][0] = __float_as_uint(hid[(r1m + rA) * 68 + cA]);
            a[1][1] = __float_as_uint(hid[(r1m + 8 + rA) * 68 + cA]);
            a[1][2] = __float_as_uint(hid[(r1m + rA) * 68 + cA + 4]);
            a[1][3] = __float_as_uint(hid[(r1m + 8 + rA) * 68 + cA + 4]);
            #pragma unroll
            for (int nt = 0; nt < 4; nt++) {
                float2 b = fW2[(kt * 8 + nhE * 4 + nt) * 32 + lane];
                unsigned b0 = __float_as_uint(b.x), b1 = __float_as_uint(b.y);
                MMA_TF32(acc[0][nt], a[0], b0, b1);
                MMA_TF32(acc[1][nt], a[1], b0, b1);
            }
        }
        {
            int cbv = 2 * (lane & 3);
            #pragma unroll
            for (int s2 = 0; s2 < 2; s2++) {
                int rb = (s2 ? r1m : r0m) + rA;
                #pragma unroll
                for (int nt = 0; nt < 4; nt++) {
                    int col = n0b + nt * 8 + cbv;
                    float v0, v1, v2, v3;
                    if (isA) {
                        v0 = __expf(fmaxf(acc[s2][nt][0], 0.f));
                        v1 = __expf(fmaxf(acc[s2][nt][1], 0.f));
                        v2 = __expf(fmaxf(acc[s2][nt][2], 0.f));
                        v3 = __expf(fmaxf(acc[s2][nt][3], 0.f));
                    } else {
                        v0 = fmaxf(acc[s2][nt][0], 0.f);
                        v1 = fmaxf(acc[s2][nt][1], 0.f);
                        v2 = fmaxf(acc[s2][nt][2], 0.f);
                        v3 = fmaxf(acc[s2][nt][3], 0.f);
                    }
                    res[rb * 68 + col]           = v0;
                    res[rb * 68 + col + 1]       = v1;
                    res[(rb + 8) * 68 + col]     = v2;
                    res[(rb + 8) * 68 + col + 1] = v3;
                }
            }
        }
        __syncthreads();
    }

    // ===== pipeline drain: scatter of the final tile =====
    #pragma unroll
    for (int k = 0; k < 4; k++) {
        int d = dPrev[k];
        if (d >= 0) {
            int e = slot + 16 * k;
            float4 ex = *(const float4*)(exA + e * 68 + js);
            float4 dl = *(const float4*)(dlP + e * 68 + js);
            float4 vv = *(const float4*)(g_v + (size_t)sPrev[k] * C + js);
            float4 nv;
            nv.x = ex.x * (vv.x + dl.x);
            nv.y = ex.y * (vv.y + dl.y);
            nv.z = ex.z * (vv.z + dl.z);
            nv.w = ex.w * (vv.w + dl.w);
            RED_V4(g_num + (size_t)d * C + js, nv);
            RED_V4(g_den + (size_t)d * C + js, ex);
        }
    }
}

// ---------------- K3: out kernel — tf32 MMA over 64-node tiles ------------------
__global__ void __launch_bounds__(256)
out_kernel(const float* __restrict__ b_out, float* __restrict__ out, int n)
{
    __shared__ float rs[64 * 68];
    int tid  = threadIdx.x;
    int lane = tid & 31;
    int wid  = tid >> 5;
    int base = blockIdx.x * 64;

    for (int t = tid; t < 1024; t += 256) {
        int row = t >> 4;
        int col = (t & 15) * 4;
        int node = base + row;
        float4 r = make_float4(0.f, 0.f, 0.f, 0.f);
        if (node < n) {
            float4 nu = *(const float4*)(g_num + (size_t)node * C + col);
            float4 de = *(const float4*)(g_den + (size_t)node * C + col);
            r.x = __uint_as_float(f2tf32(nu.x / (de.x + 1e-16f)));
            r.y = __uint_as_float(f2tf32(nu.y / (de.y + 1e-16f)));
            r.z = __uint_as_float(f2tf32(nu.z / (de.z + 1e-16f)));
            r.w = __uint_as_float(f2tf32(nu.w / (de.w + 1e-16f)));
        }
        *(float4*)(rs + row * 68 + col) = r;
    }
    __syncthreads();

    int r0 = (wid & 3) * 16;
    int nh = wid >> 2;
    int n0 = nh * 32;
    int rA = lane >> 2;
    int cb = 2 * (lane & 3);
    int rowg0 = base + r0 + rA;
    int rowg1 = rowg0 + 8;

    float acc[4][4];
    #pragma unroll
    for (int nt = 0; nt < 4; nt++) {
        int col = n0 + nt * 8 + cb;
        float b0 = b_out[col], b1 = b_out[col + 1];
        acc[nt][0] = b0; acc[nt][1] = b1; acc[nt][2] = b0; acc[nt][3] = b1;
    }
    #pragma unroll
    for (int kt = 0; kt < 8; kt++) {
        int cA = kt * 8 + (lane & 3);
        unsigned a[4];
        a[0] = __float_as_uint(rs[(r0 + rA) * 68 + cA]);
        a[1] = __float_as_uint(rs[(r0 + 8 + rA) * 68 + cA]);
        a[2] = __float_as_uint(rs[(r0 + rA) * 68 + cA + 4]);
        a[3] = __float_as_uint(rs[(r0 + 8 + rA) * 68 + cA + 4]);
        #pragma unroll
        for (int nt = 0; nt < 4; nt++) {
            float2 b = ((const float2*)g_fWout)[(kt * 8 + nh * 4 + nt) * 32 + lane];
            MMA_TF32(acc[nt], a, __float_as_uint(b.x), __float_as_uint(b.y));
        }
    }
    #pragma unroll
    for (int nt = 0; nt < 4; nt++) {
        int col = n0 + nt * 8 + cb;
        if (rowg0 < n)
            *(float2*)(out + (size_t)rowg0 * C + col) =
                make_float2(fmaxf(acc[nt][0], 0.f), fmaxf(acc[nt][1], 0.f));
        if (rowg1 < n)
            *(float2*)(out + (size_t)rowg1 * C + col) =
                make_float2(fmaxf(acc[nt][2], 0.f), fmaxf(acc[nt][3], 0.f));
    }
}

// ---------------- launch --------------------------------------------------------
extern "C" void kernel_launch(void* const* d_in, const int* in_sizes, int n_in,
                              void* d_out, int out_size)
{
    const float* x      = (const float*)d_in[0];
    const float* pos    = (const float*)d_in[1];
    const int*   ei     = (const int*)  d_in[2];
    const float* W_in   = (const float*)d_in[3];
    const float* b_in   = (const float*)d_in[4];
    const float* W_out  = (const float*)d_in[5];
    const float* b_out  = (const float*)d_in[6];
    const float* W_lin  = (const float*)d_in[7];
    const float* W_src  = (const float*)d_in[8];
    const float* W_dst  = (const float*)d_in[9];
    const float* pos_w1 = (const float*)d_in[10];
    const float* pos_b1 = (const float*)d_in[11];
    const float* pos_w2 = (const float*)d_in[12];
    const float* pos_b2 = (const float*)d_in[13];
    const float* att_w1 = (const float*)d_in[14];
    const float* att_b1 = (const float*)d_in[15];
    const float* att_w2 = (const float*)d_in[16];
    const float* att_b2 = (const float*)d_in[17];

    int n = in_sizes[0] / C;
    int E = in_sizes[2] / 2;
    const int* srcArr = ei;
    const int* dstArr = ei + E;

    size_t smemNode = (size_t)(3 * 64 * 68) * sizeof(float);          // 52224
    size_t smemEdge = (size_t)(4 * 64 * 68) * sizeof(float) + 1024;   // 70656
    cudaFuncSetAttribute(node_kernel, cudaFuncAttributeMaxDynamicSharedMemorySize, (int)smemNode);
    cudaFuncSetAttribute(edge_kernel, cudaFuncAttributeMaxDynamicSharedMemorySize, (int)smemEdge);

    int tilesN = (n + 63) / 64;

    prep_kernel<<<1, 256>>>(att_w1, W_dst, W_src, W_in, W_lin, att_w2, pos_w2, W_out,
                            pos_b1, pos_b2);
    node_kernel<<<tilesN, 256, smemNode>>>(x, pos, pos_w1, b_in, att_b1, att_b2, n);
    spacer_kernel<<<1, 32>>>();   // puts edge_kernel at launch #4 (ncu capture slot)
    edge_kernel<<<444, 256, smemEdge>>>(srcArr, dstArr, att_b1, pos_b1, att_b2, pos_b2, E);
    out_kernel<<<tilesN, 256>>>(b_out, (float*)d_out, n);
}

// round 10
// speedup vs baseline: 1.2377x; 1.2377x over previous
#include <cuda_runtime.h>
#include <cuda_fp16.h>
#include <cstdint>

#define C 64
#define MAXN 50000
#define MAXE 800000

// ---------------- device scratch (static: no allocation allowed) ----------------
__device__ float g_v[MAXN * C];
__device__ float g_Q1[MAXN * C];
__device__ float g_K1[MAXN * C];
__device__ float g_P1[MAXN * C];
__device__ float g_num[MAXN * C];
__device__ float g_den[MAXN * C];
__device__ float g_Mq_t[C * C];
__device__ float g_Mk_t[C * C];
__device__ float g_Win_t[C * C];
__device__ float g_Wlin_t[C * C];
__device__ float g_w2a_t[C * C];
__device__ float g_w2p_t[C * C];
__device__ float g_Wout_t[C * C];
__device__ float g_delta0[C];
__device__ float g_fWin[4096];
__device__ float g_fWlin[4096];
__device__ float g_fMq[4096];
__device__ float g_fMk[4096];
__device__ float g_fW2a[4096];
__device__ float g_fWout[4096];
// fp16 B fragments for edge MLP-2 GEMMs: [(kt*8+nt)*32+lane] -> uint2 {b0,b1}
__device__ uint2 g_hW2a[1024];
__device__ uint2 g_hW2p[1024];

__device__ __forceinline__ unsigned f2tf32(float f) {
    unsigned r;
    asm("cvt.rna.tf32.f32 %0, %1;" : "=r"(r) : "f"(f));
    return r;
}
__device__ __forceinline__ unsigned pack_h2(float a, float b) {
    __half2 h = __floats2half2_rn(a, b);
    return *reinterpret_cast<unsigned*>(&h);
}

#define MMA_TF32(d, a, b0, b1)                                               \
    asm volatile("mma.sync.aligned.m16n8k8.row.col.f32.tf32.tf32.f32 "       \
                 "{%0,%1,%2,%3}, {%4,%5,%6,%7}, {%8,%9}, {%0,%1,%2,%3};"     \
                 : "+f"(d[0]), "+f"(d[1]), "+f"(d[2]), "+f"(d[3])            \
                 : "r"(a[0]), "r"(a[1]), "r"(a[2]), "r"(a[3]),               \
                   "r"(b0), "r"(b1))

#define MMA_F16(d, a, b0, b1)                                                \
    asm volatile("mma.sync.aligned.m16n8k16.row.col.f32.f16.f16.f32 "        \
                 "{%0,%1,%2,%3}, {%4,%5,%6,%7}, {%8,%9}, {%0,%1,%2,%3};"     \
                 : "+f"(d[0]), "+f"(d[1]), "+f"(d[2]), "+f"(d[3])            \
                 : "r"(a[0]), "r"(a[1]), "r"(a[2]), "r"(a[3]),               \
                   "r"(b0), "r"(b1))

#define RED_V4(ptr, v)                                                       \
    asm volatile("red.global.add.v4.f32 [%0], {%1,%2,%3,%4};"                \
                 :: "l"(ptr), "f"((v).x), "f"((v).y), "f"((v).z), "f"((v).w) \
                 : "memory")

// ---------------- K0: weight prep ------------------------------------------------
__global__ void prep_kernel(const float* __restrict__ att_w1,
                            const float* __restrict__ W_dst,
                            const float* __restrict__ W_src,
                            const float* __restrict__ W_in,
                            const float* __restrict__ W_lin,
                            const float* __restrict__ att_w2,
                            const float* __restrict__ pos_w2,
                            const float* __restrict__ W_out,
                            const float* __restrict__ pos_b1,
                            const float* __restrict__ pos_b2)
{
    __shared__ float s_a[C * C];
    __shared__ float s_d[C * C];
    __shared__ float s_s[C * C];
    int tid = threadIdx.x;
    for (int t = tid; t < C * C; t += blockDim.x) {
        s_a[t] = att_w1[t];
        s_d[t] = W_dst[t];
        s_s[t] = W_src[t];
    }
    __syncthreads();
    for (int idx = tid; idx < C * C; idx += blockDim.x) {
        int t = idx >> 6, j = idx & 63;
        float aq = 0.f, ak = 0.f;
        #pragma unroll 8
        for (int u = 0; u < C; u++) {
            float a = s_a[t * C + u];
            aq = fmaf(a, s_d[u * C + j], aq);
            ak = fmaf(a, s_s[u * C + j], ak);
        }
        g_Mq_t[j * C + t] = aq;
        g_Mk_t[j * C + t] = ak;
    }
    for (int idx = tid; idx < C * C; idx += blockDim.x) {
        int cc = idx >> 6, j = idx & 63;
        g_Win_t[j * C + cc]  = W_in[idx];
        g_Wlin_t[j * C + cc] = W_lin[idx];
        g_w2a_t[j * C + cc]  = att_w2[idx];
        g_w2p_t[j * C + cc]  = pos_w2[idx];
        g_Wout_t[j * C + cc] = W_out[idx];
    }
    if (tid < C) {
        float acc = pos_b2[tid];
        #pragma unroll 8
        for (int j = 0; j < C; j++)
            acc = fmaf(fmaxf(pos_b1[j], 0.f), pos_w2[tid * C + j], acc);
        g_delta0[tid] = fmaxf(acc, 0.f);
    }
    __syncthreads();
    for (int t = tid; t < 2048; t += blockDim.x) {
        int kt   = t >> 8;
        int nt   = (t >> 5) & 7;
        int lane = t & 31;
        int kr = kt * 8 + (lane & 3);
        int nc = nt * 8 + (lane >> 2);
        int lo = kr * 64 + nc, hi = (kr + 4) * 64 + nc;
        ((float2*)g_fWin)[t]  = make_float2(__uint_as_float(f2tf32(g_Win_t[lo])),
                                            __uint_as_float(f2tf32(g_Win_t[hi])));
        ((float2*)g_fWlin)[t] = make_float2(__uint_as_float(f2tf32(g_Wlin_t[lo])),
                                            __uint_as_float(f2tf32(g_Wlin_t[hi])));
        ((float2*)g_fMq)[t]   = make_float2(__uint_as_float(f2tf32(g_Mq_t[lo])),
                                            __uint_as_float(f2tf32(g_Mq_t[hi])));
        ((float2*)g_fMk)[t]   = make_float2(__uint_as_float(f2tf32(g_Mk_t[lo])),
                                            __uint_as_float(f2tf32(g_Mk_t[hi])));
        ((float2*)g_fW2a)[t]  = make_float2(__uint_as_float(f2tf32(g_w2a_t[lo])),
                                            __uint_as_float(f2tf32(g_w2a_t[hi])));
        ((float2*)g_fWout)[t] = make_float2(__uint_as_float(f2tf32(g_Wout_t[lo])),
                                            __uint_as_float(f2tf32(g_Wout_t[hi])));
    }
    // fp16 B fragments for edge kernel (m16n8k16): b0 = k{tig*2,+1}, b1 = k{+8,+9}
    for (int t = tid; t < 1024; t += blockDim.x) {
        int kt   = t >> 8;          // 0..3 (k16 steps)
        int nt   = (t >> 5) & 7;    // 0..7
        int lane = t & 31;
        int tig = lane & 3, gid = lane >> 2;
        int n  = nt * 8 + gid;
        int k0 = kt * 16 + tig * 2;
        uint2 ua, up;
        ua.x = pack_h2(g_w2a_t[k0 * 64 + n],       g_w2a_t[(k0 + 1) * 64 + n]);
        ua.y = pack_h2(g_w2a_t[(k0 + 8) * 64 + n], g_w2a_t[(k0 + 9) * 64 + n]);
        up.x = pack_h2(g_w2p_t[k0 * 64 + n],       g_w2p_t[(k0 + 1) * 64 + n]);
        up.y = pack_h2(g_w2p_t[(k0 + 8) * 64 + n], g_w2p_t[(k0 + 9) * 64 + n]);
        g_hW2a[t] = ua;
        g_hW2p[t] = up;
    }
}

// ---------------- dummy (instrumentation spacer so ncu window hits edge_kernel) --
__global__ void spacer_kernel() {}

// ---------------- K1: node kernel — 5 fused tf32 GEMMs over 64-node tiles -------
__global__ void __launch_bounds__(256)
node_kernel(const float* __restrict__ x,
            const float* __restrict__ pos,
            const float* __restrict__ pos_w1,
            const float* __restrict__ b_in,
            const float* __restrict__ att_b1,
            const float* __restrict__ att_b2,
            int n)
{
    extern __shared__ float sm[];
    float* xs = sm;
    float* hs = sm + 4352;
    float* vs = sm + 8704;
    int tid  = threadIdx.x;
    int lane = tid & 31;
    int wid  = tid >> 5;
    int base = blockIdx.x * 64;

    for (int t = tid; t < 1024; t += 256) {
        int row = t >> 4;
        int col = (t & 15) * 4;
        int node = base + row;
        float4 v4 = make_float4(0.f, 0.f, 0.f, 0.f);
        if (node < n) v4 = *(const float4*)(x + (size_t)node * C + col);
        float4 r;
        r.x = __uint_as_float(f2tf32(v4.x));
        r.y = __uint_as_float(f2tf32(v4.y));
        r.z = __uint_as_float(f2tf32(v4.z));
        r.w = __uint_as_float(f2tf32(v4.w));
        *(float4*)(xs + row * 68 + col) = r;
    }
    {
        int row = tid >> 2;
        int node = base + row;
        if (node < n) {
            float px = pos[(size_t)node * 3 + 0];
            float py = pos[(size_t)node * 3 + 1];
            float pz = pos[(size_t)node * 3 + 2];
            int c0 = (tid & 3) * 16;
            #pragma unroll
            for (int c = c0; c < c0 + 16; c++) {
                g_P1[(size_t)node * C + c] =
                    px * pos_w1[c * 3 + 0] + py * pos_w1[c * 3 + 1] + pz * pos_w1[c * 3 + 2];
            }
        }
    }
    __syncthreads();

    int r0 = (wid & 3) * 16;
    int nh = wid >> 2;
    int n0 = nh * 32;
    int rA = lane >> 2;
    int cb = 2 * (lane & 3);
    int rowg0 = base + r0 + rA;
    int rowg1 = rowg0 + 8;
    bool ok0 = rowg0 < n, ok1 = rowg1 < n;

    {
        float acc[4][4];
        #pragma unroll
        for (int nt = 0; nt < 4; nt++) {
            int col = n0 + nt * 8 + cb;
            float b0 = b_in[col], b1 = b_in[col + 1];
            acc[nt][0] = b0; acc[nt][1] = b1; acc[nt][2] = b0; acc[nt][3] = b1;
        }
        #pragma unroll
        for (int kt = 0; kt < 8; kt++) {
            int cA = kt * 8 + (lane & 3);
            unsigned a[4];
            a[0] = __float_as_uint(xs[(r0 + rA) * 68 + cA]);
            a[1] = __float_as_uint(xs[(r0 + 8 + rA) * 68 + cA]);
            a[2] = __float_as_uint(xs[(r0 + rA) * 68 + cA + 4]);
            a[3] = __float_as_uint(xs[(r0 + 8 + rA) * 68 + cA + 4]);
            #pragma unroll
            for (int nt = 0; nt < 4; nt++) {
                float2 b = ((const float2*)g_fWin)[(kt * 8 + nh * 4 + nt) * 32 + lane];
                MMA_TF32(acc[nt], a, __float_as_uint(b.x), __float_as_uint(b.y));
            }
        }
        #pragma unroll
        for (int nt = 0; nt < 4; nt++) {
            int col = n0 + nt * 8 + cb;
            hs[(r0 + rA) * 68 + col]       = __uint_as_float(f2tf32(fmaxf(acc[nt][0], 0.f)));
            hs[(r0 + rA) * 68 + col + 1]   = __uint_as_float(f2tf32(fmaxf(acc[nt][1], 0.f)));
            hs[(r0 + 8 + rA) * 68 + col]     = __uint_as_float(f2tf32(fmaxf(acc[nt][2], 0.f)));
            hs[(r0 + 8 + rA) * 68 + col + 1] = __uint_as_float(f2tf32(fmaxf(acc[nt][3], 0.f)));
        }
    }
    __syncthreads();

    {
        float acc[4][4];
        #pragma unroll
        for (int nt = 0; nt < 4; nt++)
            #pragma unroll
            for (int q = 0; q < 4; q++) acc[nt][q] = 0.f;
        #pragma unroll
        for (int kt = 0; kt < 8; kt++) {
            int cA = kt * 8 + (lane & 3);
            unsigned a[4];
            a[0] = __float_as_uint(hs[(r0 + rA) * 68 + cA]);
            a[1] = __float_as_uint(hs[(r0 + 8 + rA) * 68 + cA]);
            a[2] = __float_as_uint(hs[(r0 + rA) * 68 + cA + 4]);
            a[3] = __float_as_uint(hs[(r0 + 8 + rA) * 68 + cA + 4]);
            #pragma unroll
            for (int nt = 0; nt < 4; nt++) {
                float2 b = ((const float2*)g_fWlin)[(kt * 8 + nh * 4 + nt) * 32 + lane];
                MMA_TF32(acc[nt], a, __float_as_uint(b.x), __float_as_uint(b.y));
            }
        }
        #pragma unroll
        for (int nt = 0; nt < 4; nt++) {
            int col = n0 + nt * 8 + cb;
            vs[(r0 + rA) * 68 + col]         = acc[nt][0];
            vs[(r0 + rA) * 68 + col + 1]     = acc[nt][1];
            vs[(r0 + 8 + rA) * 68 + col]     = acc[nt][2];
            vs[(r0 + 8 + rA) * 68 + col + 1] = acc[nt][3];
            if (ok0) *(float2*)(g_v + (size_t)rowg0 * C + col) = make_float2(acc[nt][0], acc[nt][1]);
            if (ok1) *(float2*)(g_v + (size_t)rowg1 * C + col) = make_float2(acc[nt][2], acc[nt][3]);
        }
    }
    {
        float aq[4][4], ak[4][4];
        #pragma unroll
        for (int nt = 0; nt < 4; nt++)
            #pragma unroll
            for (int q = 0; q < 4; q++) { aq[nt][q] = 0.f; ak[nt][q] = 0.f; }
        #pragma unroll
        for (int kt = 0; kt < 8; kt++) {
            int cA = kt * 8 + (lane & 3);
            unsigned a[4];
            a[0] = __float_as_uint(hs[(r0 + rA) * 68 + cA]);
            a[1] = __float_as_uint(hs[(r0 + 8 + rA) * 68 + cA]);
            a[2] = __float_as_uint(hs[(r0 + rA) * 68 + cA + 4]);
            a[3] = __float_as_uint(hs[(r0 + 8 + rA) * 68 + cA + 4]);
            #pragma unroll
            for (int nt = 0; nt < 4; nt++) {
                float2 bq = ((const float2*)g_fMq)[(kt * 8 + nh * 4 + nt) * 32 + lane];
                float2 bk = ((const float2*)g_fMk)[(kt * 8 + nh * 4 + nt) * 32 + lane];
                MMA_TF32(aq[nt], a, __float_as_uint(bq.x), __float_as_uint(bq.y));
                MMA_TF32(ak[nt], a, __float_as_uint(bk.x), __float_as_uint(bk.y));
            }
        }
        #pragma unroll
        for (int nt = 0; nt < 4; nt++) {
            int col = n0 + nt * 8 + cb;
            float ba0 = att_b1[col], ba1 = att_b1[col + 1];
            xs[(r0 + rA) * 68 + col]       = __uint_as_float(f2tf32(fmaxf(aq[nt][0] - ak[nt][0] + ba0, 0.f)));
            xs[(r0 + rA) * 68 + col + 1]   = __uint_as_float(f2tf32(fmaxf(aq[nt][1] - ak[nt][1] + ba1, 0.f)));
            xs[(r0 + 8 + rA) * 68 + col]     = __uint_as_float(f2tf32(fmaxf(aq[nt][2] - ak[nt][2] + ba0, 0.f)));
            xs[(r0 + 8 + rA) * 68 + col + 1] = __uint_as_float(f2tf32(fmaxf(aq[nt][3] - ak[nt][3] + ba1, 0.f)));
            if (ok0) {
                *(float2*)(g_Q1 + (size_t)rowg0 * C + col) = make_float2(aq[nt][0], aq[nt][1]);
                *(float2*)(g_K1 + (size_t)rowg0 * C + col) = make_float2(ak[nt][0], ak[nt][1]);
            }
            if (ok1) {
                *(float2*)(g_Q1 + (size_t)rowg1 * C + col) = make_float2(aq[nt][2], aq[nt][3]);
                *(float2*)(g_K1 + (size_t)rowg1 * C + col) = make_float2(ak[nt][2], ak[nt][3]);
            }
        }
    }
    __syncthreads();

    {
        float acc[4][4];
        #pragma unroll
        for (int nt = 0; nt < 4; nt++) {
            int col = n0 + nt * 8 + cb;
            float b0 = att_b2[col], b1 = att_b2[col + 1];
            acc[nt][0] = b0; acc[nt][1] = b1; acc[nt][2] = b0; acc[nt][3] = b1;
        }
        #pragma unroll
        for (int kt = 0; kt < 8; kt++) {
            int cA = kt * 8 + (lane & 3);
            unsigned a[4];
            a[0] = __float_as_uint(xs[(r0 + rA) * 68 + cA]);
            a[1] = __float_as_uint(xs[(r0 + 8 + rA) * 68 + cA]);
            a[2] = __float_as_uint(xs[(r0 + rA) * 68 + cA + 4]);
            a[3] = __float_as_uint(xs[(r0 + 8 + rA) * 68 + cA + 4]);
            #pragma unroll
            for (int nt = 0; nt < 4; nt++) {
                float2 b = ((const float2*)g_fW2a)[(kt * 8 + nh * 4 + nt) * 32 + lane];
                MMA_TF32(acc[nt], a, __float_as_uint(b.x), __float_as_uint(b.y));
            }
        }
        #pragma unroll
        for (int nt = 0; nt < 4; nt++) {
            int col = n0 + nt * 8 + cb;
            float d0 = g_delta0[col], d1 = g_delta0[col + 1];
            float e0 = __expf(fmaxf(acc[nt][0], 0.f));
            float e1 = __expf(fmaxf(acc[nt][1], 0.f));
            float e2 = __expf(fmaxf(acc[nt][2], 0.f));
            float e3 = __expf(fmaxf(acc[nt][3], 0.f));
            if (ok0) {
                float v0 = vs[(r0 + rA) * 68 + col];
                float v1 = vs[(r0 + rA) * 68 + col + 1];
                *(float2*)(g_den + (size_t)rowg0 * C + col) = make_float2(e0, e1);
                *(float2*)(g_num + (size_t)rowg0 * C + col) = make_float2(e0 * (v0 + d0), e1 * (v1 + d1));
            }
            if (ok1) {
                float v2 = vs[(r0 + 8 + rA) * 68 + col];
                float v3 = vs[(r0 + 8 + rA) * 68 + col + 1];
                *(float2*)(g_den + (size_t)rowg1 * C + col) = make_float2(e2, e3);
                *(float2*)(g_num + (size_t)rowg1 * C + col) = make_float2(e2 * (v2 + d0), e3 * (v3 + d1));
            }
        }
    }
}

// ---------------- K2: edge kernel — fp16 MMA, reg-resident B, R5 pipeline -------
// smem layout (bytes):
//   [0, 9216)        hidA16  64 rows x 72 halves
//   [9216, 18432)    hidP16
//   [18432, 35840)   exA     64 x 68 fp32
//   [35840, 53248)   dlP
//   [53248, 53760)   seB [2][64]
//   [53760, 54272)   deB [2][64]
__global__ void __launch_bounds__(256, 3)
edge_kernel(const int* __restrict__ src, const int* __restrict__ dst,
            const float* __restrict__ att_b1, const float* __restrict__ pos_b1,
            const float* __restrict__ att_b2, const float* __restrict__ pos_b2,
            int E)
{
    extern __shared__ char smE[];
    __half* hidA16 = (__half*)smE;
    __half* hidP16 = (__half*)(smE + 9216);
    float*  exA    = (float*)(smE + 18432);
    float*  dlP    = (float*)(smE + 35840);
    int*    seB    = (int*)(smE + 53248);
    int*    deB    = (int*)(smE + 53760);

    int tid  = threadIdx.x;
    int lane = tid & 31;
    int wid  = tid >> 5;
    bool isA = (wid < 4);
    int sub  = wid & 3;
    int nhE  = sub & 1;
    int n0b  = nhE * 32;
    int mp   = sub >> 1;
    int r0m  = mp * 16;
    int r1m  = (mp + 2) * 16;

    const float* b2 = isA ? att_b2 : pos_b2;
    __half* hid = isA ? hidA16 : hidP16;
    float*  res = isA ? exA    : dlP;

    // preload fp16 B fragments (reg-resident, reused every tile): 32 regs
    uint2 bB[4][4];
    {
        const uint2* hw = isA ? g_hW2a : g_hW2p;
        #pragma unroll
        for (int kt = 0; kt < 4; kt++)
            #pragma unroll
            for (int nt = 0; nt < 4; nt++)
                bB[kt][nt] = hw[((kt * 8) + nhE * 4 + nt) * 32 + lane];
    }
    float bias0[4], bias1[4];
    #pragma unroll
    for (int nt = 0; nt < 4; nt++) {
        int col = n0b + nt * 8 + 2 * (lane & 3);
        bias0[nt] = b2[col];
        bias1[nt] = b2[col + 1];
    }

    // gather/scatter role: 16-lane group owns col slice js for edges {slot+16k}
    int slot = tid >> 4;
    int js   = (tid & 15) << 2;     // fp32 col index (0,4,...,60)
    float4 ba1 = *(const float4*)(att_b1 + js);
    float4 bp1 = *(const float4*)(pos_b1 + js);

    int sPrev[4], dPrev[4];
    #pragma unroll
    for (int k = 0; k < 4; k++) dPrev[k] = -1;

    int ntiles = (E + 63) >> 6;

    {
        int base = blockIdx.x << 6;
        if (tid < 64) {
            int e = base + tid;
            seB[tid] = (e < E) ? src[e] : 0;
        } else if (tid < 128) {
            int e = base + tid - 64;
            deB[tid - 64] = (e < E) ? dst[e] : -1;
        }
    }
    __syncthreads();

    int it = 0;
    for (int tile = blockIdx.x; tile < ntiles; tile += gridDim.x, it ^= 1) {
        // ===== PHASE A: scatter(prev) + gather(cur, fp16 pack) + idx prefetch =====
        #pragma unroll
        for (int k = 0; k < 4; k++) {
            int d = dPrev[k];
            if (d >= 0) {
                int e = slot + 16 * k;
                float4 ex = *(const float4*)(exA + e * 68 + js);
                float4 dl = *(const float4*)(dlP + e * 68 + js);
                float4 vv = *(const float4*)(g_v + (size_t)sPrev[k] * C + js);
                float4 nv;
                nv.x = ex.x * (vv.x + dl.x);
                nv.y = ex.y * (vv.y + dl.y);
                nv.z = ex.z * (vv.z + dl.z);
                nv.w = ex.w * (vv.w + dl.w);
                RED_V4(g_num + (size_t)d * C + js, nv);
                RED_V4(g_den + (size_t)d * C + js, ex);
            }
        }
        #pragma unroll
        for (int k = 0; k < 4; k++) {
            int e = slot + 16 * k;
            int s = seB[it * 64 + e];
            int d = deB[it * 64 + e];
            sPrev[k] = s;
            dPrev[k] = d;
            int dc = d < 0 ? 0 : d;
            float4 qv = *(const float4*)(g_Q1 + (size_t)dc * C + js);
            float4 kv = *(const float4*)(g_K1 + (size_t)s  * C + js);
            float4 pd = *(const float4*)(g_P1 + (size_t)dc * C + js);
            float4 ps = *(const float4*)(g_P1 + (size_t)s  * C + js);
            uint2 ua, up;
            if (d >= 0) {
                ua.x = pack_h2(fmaxf(qv.x - kv.x + ba1.x, 0.f), fmaxf(qv.y - kv.y + ba1.y, 0.f));
                ua.y = pack_h2(fmaxf(qv.z - kv.z + ba1.z, 0.f), fmaxf(qv.w - kv.w + ba1.w, 0.f));
                up.x = pack_h2(fmaxf(pd.x - ps.x + bp1.x, 0.f), fmaxf(pd.y - ps.y + bp1.y, 0.f));
                up.y = pack_h2(fmaxf(pd.z - ps.z + bp1.z, 0.f), fmaxf(pd.w - ps.w + bp1.w, 0.f));
            } else {
                ua = make_uint2(0u, 0u);
                up = ua;
            }
            *(uint2*)(hidA16 + e * 72 + js) = ua;
            *(uint2*)(hidP16 + e * 72 + js) = up;
        }
        {
            int ntile = tile + gridDim.x;
            if (ntile < ntiles) {
                int base = ntile << 6;
                int ib = (it ^ 1) * 64;
                if (tid < 64) {
                    int e = base + tid;
                    seB[ib + tid] = (e < E) ? src[e] : 0;
                } else if (tid < 128) {
                    int e = base + tid - 64;
                    deB[ib + tid - 64] = (e < E) ? dst[e] : -1;
                }
            }
        }
        __syncthreads();

        // ===== PHASE B: fp16 m16n8k16 MMA + epilogue -> exA/dlP =====
        float acc[2][4][4];
        #pragma unroll
        for (int s2 = 0; s2 < 2; s2++)
            #pragma unroll
            for (int nt = 0; nt < 4; nt++) {
                acc[s2][nt][0] = bias0[nt];
                acc[s2][nt][1] = bias1[nt];
                acc[s2][nt][2] = bias0[nt];
                acc[s2][nt][3] = bias1[nt];
            }
        int rA = lane >> 2;
        #pragma unroll
        for (int kt = 0; kt < 4; kt++) {
            int colh = kt * 16 + (lane & 3) * 2;   // half index within row
            unsigned a[2][4];
            a[0][0] = *(const unsigned*)(hid + (r0m + rA) * 72 + colh);
            a[0][1] = *(const unsigned*)(hid + (r0m + 8 + rA) * 72 + colh);
            a[0][2] = *(const unsigned*)(hid + (r0m + rA) * 72 + colh + 8);
            a[0][3] = *(const unsigned*)(hid + (r0m + 8 + rA) * 72 + colh + 8);
            a[1][0] = *(const unsigned*)(hid + (r1m + rA) * 72 + colh);
            a[1][1] = *(const unsigned*)(hid + (r1m + 8 + rA) * 72 + colh);
            a[1][2] = *(const unsigned*)(hid + (r1m + rA) * 72 + colh + 8);
            a[1][3] = *(const unsigned*)(hid + (r1m + 8 + rA) * 72 + colh + 8);
            #pragma unroll
            for (int nt = 0; nt < 4; nt++) {
                MMA_F16(acc[0][nt], a[0], bB[kt][nt].x, bB[kt][nt].y);
                MMA_F16(acc[1][nt], a[1], bB[kt][nt].x, bB[kt][nt].y);
            }
        }
        {
            int cbv = 2 * (lane & 3);
            #pragma unroll
            for (int s2 = 0; s2 < 2; s2++) {
                int rb = (s2 ? r1m : r0m) + rA;
                #pragma unroll
                for (int nt = 0; nt < 4; nt++) {
                    int col = n0b + nt * 8 + cbv;
                    float v0, v1, v2, v3;
                    if (isA) {
                        v0 = __expf(fmaxf(acc[s2][nt][0], 0.f));
                        v1 = __expf(fmaxf(acc[s2][nt][1], 0.f));
                        v2 = __expf(fmaxf(acc[s2][nt][2], 0.f));
                        v3 = __expf(fmaxf(acc[s2][nt][3], 0.f));
                    } else {
                        v0 = fmaxf(acc[s2][nt][0], 0.f);
                        v1 = fmaxf(acc[s2][nt][1], 0.f);
                        v2 = fmaxf(acc[s2][nt][2], 0.f);
                        v3 = fmaxf(acc[s2][nt][3], 0.f);
                    }
                    res[rb * 68 + col]           = v0;
                    res[rb * 68 + col + 1]       = v1;
                    res[(rb + 8) * 68 + col]     = v2;
                    res[(rb + 8) * 68 + col + 1] = v3;
                }
            }
        }
        __syncthreads();
    }

    // ===== pipeline drain: scatter of the final tile =====
    #pragma unroll
    for (int k = 0; k < 4; k++) {
        int d = dPrev[k];
        if (d >= 0) {
            int e = slot + 16 * k;
            float4 ex = *(const float4*)(exA + e * 68 + js);
            float4 dl = *(const float4*)(dlP + e * 68 + js);
            float4 vv = *(const float4*)(g_v + (size_t)sPrev[k] * C + js);
            float4 nv;
            nv.x = ex.x * (vv.x + dl.x);
            nv.y = ex.y * (vv.y + dl.y);
            nv.z = ex.z * (vv.z + dl.z);
            nv.w = ex.w * (vv.w + dl.w);
            RED_V4(g_num + (size_t)d * C + js, nv);
            RED_V4(g_den + (size_t)d * C + js, ex);
        }
    }
}

// ---------------- K3: out kernel — tf32 MMA over 64-node tiles ------------------
__global__ void __launch_bounds__(256)
out_kernel(const float* __restrict__ b_out, float* __restrict__ out, int n)
{
    __shared__ float rs[64 * 68];
    int tid  = threadIdx.x;
    int lane = tid & 31;
    int wid  = tid >> 5;
    int base = blockIdx.x * 64;

    for (int t = tid; t < 1024; t += 256) {
        int row = t >> 4;
        int col = (t & 15) * 4;
        int node = base + row;
        float4 r = make_float4(0.f, 0.f, 0.f, 0.f);
        if (node < n) {
            float4 nu = *(const float4*)(g_num + (size_t)node * C + col);
            float4 de = *(const float4*)(g_den + (size_t)node * C + col);
            r.x = __uint_as_float(f2tf32(nu.x / (de.x + 1e-16f)));
            r.y = __uint_as_float(f2tf32(nu.y / (de.y + 1e-16f)));
            r.z = __uint_as_float(f2tf32(nu.z / (de.z + 1e-16f)));
            r.w = __uint_as_float(f2tf32(nu.w / (de.w + 1e-16f)));
        }
        *(float4*)(rs + row * 68 + col) = r;
    }
    __syncthreads();

    int r0 = (wid & 3) * 16;
    int nh = wid >> 2;
    int n0 = nh * 32;
    int rA = lane >> 2;
    int cb = 2 * (lane & 3);
    int rowg0 = base + r0 + rA;
    int rowg1 = rowg0 + 8;

    float acc[4][4];
    #pragma unroll
    for (int nt = 0; nt < 4; nt++) {
        int col = n0 + nt * 8 + cb;
        float b0 = b_out[col], b1 = b_out[col + 1];
        acc[nt][0] = b0; acc[nt][1] = b1; acc[nt][2] = b0; acc[nt][3] = b1;
    }
    #pragma unroll
    for (int kt = 0; kt < 8; kt++) {
        int cA = kt * 8 + (lane & 3);
        unsigned a[4];
        a[0] = __float_as_uint(rs[(r0 + rA) * 68 + cA]);
        a[1] = __float_as_uint(rs[(r0 + 8 + rA) * 68 + cA]);
        a[2] = __float_as_uint(rs[(r0 + rA) * 68 + cA + 4]);
        a[3] = __float_as_uint(rs[(r0 + 8 + rA) * 68 + cA + 4]);
        #pragma unroll
        for (int nt = 0; nt < 4; nt++) {
            float2 b = ((const float2*)g_fWout)[(kt * 8 + nh * 4 + nt) * 32 + lane];
            MMA_TF32(acc[nt], a, __float_as_uint(b.x), __float_as_uint(b.y));
        }
    }
    #pragma unroll
    for (int nt = 0; nt < 4; nt++) {
        int col = n0 + nt * 8 + cb;
        if (rowg0 < n)
            *(float2*)(out + (size_t)rowg0 * C + col) =
                make_float2(fmaxf(acc[nt][0], 0.f), fmaxf(acc[nt][1], 0.f));
        if (rowg1 < n)
            *(float2*)(out + (size_t)rowg1 * C + col) =
                make_float2(fmaxf(acc[nt][2], 0.f), fmaxf(acc[nt][3], 0.f));
    }
}

// ---------------- launch --------------------------------------------------------
extern "C" void kernel_launch(void* const* d_in, const int* in_sizes, int n_in,
                              void* d_out, int out_size)
{
    const float* x      = (const float*)d_in[0];
    const float* pos    = (const float*)d_in[1];
    const int*   ei     = (const int*)  d_in[2];
    const float* W_in   = (const float*)d_in[3];
    const float* b_in   = (const float*)d_in[4];
    const float* W_out  = (const float*)d_in[5];
    const float* b_out  = (const float*)d_in[6];
    const float* W_lin  = (const float*)d_in[7];
    const float* W_src  = (const float*)d_in[8];
    const float* W_dst  = (const float*)d_in[9];
    const float* pos_w1 = (const float*)d_in[10];
    const float* pos_b1 = (const float*)d_in[11];
    const float* pos_w2 = (const float*)d_in[12];
    const float* pos_b2 = (const float*)d_in[13];
    const float* att_w1 = (const float*)d_in[14];
    const float* att_b1 = (const float*)d_in[15];
    const float* att_w2 = (const float*)d_in[16];
    const float* att_b2 = (const float*)d_in[17];

    int n = in_sizes[0] / C;
    int E = in_sizes[2] / 2;
    const int* srcArr = ei;
    const int* dstArr = ei + E;

    size_t smemNode = (size_t)(3 * 64 * 68) * sizeof(float);   // 52224
    size_t smemEdge = 54272;
    cudaFuncSetAttribute(node_kernel, cudaFuncAttributeMaxDynamicSharedMemorySize, (int)smemNode);
    cudaFuncSetAttribute(edge_kernel, cudaFuncAttributeMaxDynamicSharedMemorySize, (int)smemEdge);

    int tilesN = (n + 63) / 64;

    prep_kernel<<<1, 256>>>(att_w1, W_dst, W_src, W_in, W_lin, att_w2, pos_w2, W_out,
                            pos_b1, pos_b2);
    node_kernel<<<tilesN, 256, smemNode>>>(x, pos, pos_w1, b_in, att_b1, att_b2, n);
    spacer_kernel<<<1, 32>>>();   // keeps edge_kernel at launch #4 (ncu capture slot)
    edge_kernel<<<444, 256, smemEdge>>>(srcArr, dstArr, att_b1, pos_b1, att_b2, pos_b2, E);
    out_kernel<<<tilesN, 256>>>(b_out, (float*)d_out, n);
}

// round 11
// speedup vs baseline: 1.3344x; 1.0781x over previous
#include <cuda_runtime.h>
#include <cuda_fp16.h>
#include <cstdint>

#define C 64
#define MAXN 50000
#define MAXE 800000

// ---------------- device scratch (static: no allocation allowed) ----------------
__device__ float g_v[MAXN * C];
__device__ float g_Q1[MAXN * C];
__device__ float g_K1[MAXN * C];
__device__ float4 g_pos4[MAXN];
__device__ float g_num[MAXN * C];
__device__ float g_den[MAXN * C];
__device__ float g_Mq_t[C * C];
__device__ float g_Mk_t[C * C];
__device__ float g_Win_t[C * C];
__device__ float g_Wlin_t[C * C];
__device__ float g_w2a_t[C * C];
__device__ float g_w2p_t[C * C];
__device__ float g_Wout_t[C * C];
__device__ float g_delta0[C];
__device__ float g_fWin[4096];
__device__ float g_fWlin[4096];
__device__ float g_fMq[4096];
__device__ float g_fMk[4096];
__device__ float g_fW2a[4096];
__device__ float g_fWout[4096];
// fp16 B fragments for edge MLP-2 GEMMs: [(kt*8+nt)*32+lane] -> uint2 {b0,b1}
__device__ uint2 g_hW2a[1024];
__device__ uint2 g_hW2p[1024];

__device__ __forceinline__ unsigned f2tf32(float f) {
    unsigned r;
    asm("cvt.rna.tf32.f32 %0, %1;" : "=r"(r) : "f"(f));
    return r;
}
__device__ __forceinline__ unsigned pack_h2(float a, float b) {
    __half2 h = __floats2half2_rn(a, b);
    return *reinterpret_cast<unsigned*>(&h);
}

#define MMA_TF32(d, a, b0, b1)                                               \
    asm volatile("mma.sync.aligned.m16n8k8.row.col.f32.tf32.tf32.f32 "       \
                 "{%0,%1,%2,%3}, {%4,%5,%6,%7}, {%8,%9}, {%0,%1,%2,%3};"     \
                 : "+f"(d[0]), "+f"(d[1]), "+f"(d[2]), "+f"(d[3])            \
                 : "r"(a[0]), "r"(a[1]), "r"(a[2]), "r"(a[3]),               \
                   "r"(b0), "r"(b1))

#define MMA_F16(d, a, b0, b1)                                                \
    asm volatile("mma.sync.aligned.m16n8k16.row.col.f32.f16.f16.f32 "        \
                 "{%0,%1,%2,%3}, {%4,%5,%6,%7}, {%8,%9}, {%0,%1,%2,%3};"     \
                 : "+f"(d[0]), "+f"(d[1]), "+f"(d[2]), "+f"(d[3])            \
                 : "r"(a[0]), "r"(a[1]), "r"(a[2]), "r"(a[3]),               \
                   "r"(b0), "r"(b1))

#define RED_V4(ptr, v)                                                       \
    asm volatile("red.global.add.v4.f32 [%0], {%1,%2,%3,%4};"                \
                 :: "l"(ptr), "f"((v).x), "f"((v).y), "f"((v).z), "f"((v).w) \
                 : "memory")

__device__ __forceinline__ void ldsm_x4(unsigned& r0, unsigned& r1,
                                        unsigned& r2, unsigned& r3, unsigned addr) {
    asm volatile("ldmatrix.sync.aligned.m8n8.x4.shared.b16 {%0,%1,%2,%3}, [%4];"
                 : "=r"(r0), "=r"(r1), "=r"(r2), "=r"(r3) : "r"(addr));
}

// ---------------- K0: weight prep ------------------------------------------------
__global__ void prep_kernel(const float* __restrict__ att_w1,
                            const float* __restrict__ W_dst,
                            const float* __restrict__ W_src,
                            const float* __restrict__ W_in,
                            const float* __restrict__ W_lin,
                            const float* __restrict__ att_w2,
                            const float* __restrict__ pos_w2,
                            const float* __restrict__ W_out,
                            const float* __restrict__ pos_b1,
                            const float* __restrict__ pos_b2)
{
    __shared__ float s_a[C * C];
    __shared__ float s_d[C * C];
    __shared__ float s_s[C * C];
    int tid = threadIdx.x;
    for (int t = tid; t < C * C; t += blockDim.x) {
        s_a[t] = att_w1[t];
        s_d[t] = W_dst[t];
        s_s[t] = W_src[t];
    }
    __syncthreads();
    for (int idx = tid; idx < C * C; idx += blockDim.x) {
        int t = idx >> 6, j = idx & 63;
        float aq = 0.f, ak = 0.f;
        #pragma unroll 8
        for (int u = 0; u < C; u++) {
            float a = s_a[t * C + u];
            aq = fmaf(a, s_d[u * C + j], aq);
            ak = fmaf(a, s_s[u * C + j], ak);
        }
        g_Mq_t[j * C + t] = aq;
        g_Mk_t[j * C + t] = ak;
    }
    for (int idx = tid; idx < C * C; idx += blockDim.x) {
        int cc = idx >> 6, j = idx & 63;
        g_Win_t[j * C + cc]  = W_in[idx];
        g_Wlin_t[j * C + cc] = W_lin[idx];
        g_w2a_t[j * C + cc]  = att_w2[idx];
        g_w2p_t[j * C + cc]  = pos_w2[idx];
        g_Wout_t[j * C + cc] = W_out[idx];
    }
    if (tid < C) {
        float acc = pos_b2[tid];
        #pragma unroll 8
        for (int j = 0; j < C; j++)
            acc = fmaf(fmaxf(pos_b1[j], 0.f), pos_w2[tid * C + j], acc);
        g_delta0[tid] = fmaxf(acc, 0.f);
    }
    __syncthreads();
    for (int t = tid; t < 2048; t += blockDim.x) {
        int kt   = t >> 8;
        int nt   = (t >> 5) & 7;
        int lane = t & 31;
        int kr = kt * 8 + (lane & 3);
        int nc = nt * 8 + (lane >> 2);
        int lo = kr * 64 + nc, hi = (kr + 4) * 64 + nc;
        ((float2*)g_fWin)[t]  = make_float2(__uint_as_float(f2tf32(g_Win_t[lo])),
                                            __uint_as_float(f2tf32(g_Win_t[hi])));
        ((float2*)g_fWlin)[t] = make_float2(__uint_as_float(f2tf32(g_Wlin_t[lo])),
                                            __uint_as_float(f2tf32(g_Wlin_t[hi])));
        ((float2*)g_fMq)[t]   = make_float2(__uint_as_float(f2tf32(g_Mq_t[lo])),
                                            __uint_as_float(f2tf32(g_Mq_t[hi])));
        ((float2*)g_fMk)[t]   = make_float2(__uint_as_float(f2tf32(g_Mk_t[lo])),
                                            __uint_as_float(f2tf32(g_Mk_t[hi])));
        ((float2*)g_fW2a)[t]  = make_float2(__uint_as_float(f2tf32(g_w2a_t[lo])),
                                            __uint_as_float(f2tf32(g_w2a_t[hi])));
        ((float2*)g_fWout)[t] = make_float2(__uint_as_float(f2tf32(g_Wout_t[lo])),
                                            __uint_as_float(f2tf32(g_Wout_t[hi])));
    }
    // fp16 B fragments for edge kernel (m16n8k16)
    for (int t = tid; t < 1024; t += blockDim.x) {
        int kt   = t >> 8;
        int nt   = (t >> 5) & 7;
        int lane = t & 31;
        int tig = lane & 3, gid = lane >> 2;
        int n  = nt * 8 + gid;
        int k0 = kt * 16 + tig * 2;
        uint2 ua, up;
        ua.x = pack_h2(g_w2a_t[k0 * 64 + n],       g_w2a_t[(k0 + 1) * 64 + n]);
        ua.y = pack_h2(g_w2a_t[(k0 + 8) * 64 + n], g_w2a_t[(k0 + 9) * 64 + n]);
        up.x = pack_h2(g_w2p_t[k0 * 64 + n],       g_w2p_t[(k0 + 1) * 64 + n]);
        up.y = pack_h2(g_w2p_t[(k0 + 8) * 64 + n], g_w2p_t[(k0 + 9) * 64 + n]);
        g_hW2a[t] = ua;
        g_hW2p[t] = up;
    }
}

// ---------------- dummy (instrumentation spacer so ncu window hits edge_kernel) --
__global__ void spacer_kernel() {}

// ---------------- K1: node kernel — 4 fused tf32 GEMMs over 64-node tiles -------
__global__ void __launch_bounds__(256)
node_kernel(const float* __restrict__ x,
            const float* __restrict__ pos,
            const float* __restrict__ b_in,
            const float* __restrict__ att_b1,
            const float* __restrict__ att_b2,
            int n)
{
    extern __shared__ float sm[];
    float* xs = sm;
    float* hs = sm + 4352;
    float* vs = sm + 8704;
    int tid  = threadIdx.x;
    int lane = tid & 31;
    int wid  = tid >> 5;
    int base = blockIdx.x * 64;

    for (int t = tid; t < 1024; t += 256) {
        int row = t >> 4;
        int col = (t & 15) * 4;
        int node = base + row;
        float4 v4 = make_float4(0.f, 0.f, 0.f, 0.f);
        if (node < n) v4 = *(const float4*)(x + (size_t)node * C + col);
        float4 r;
        r.x = __uint_as_float(f2tf32(v4.x));
        r.y = __uint_as_float(f2tf32(v4.y));
        r.z = __uint_as_float(f2tf32(v4.z));
        r.w = __uint_as_float(f2tf32(v4.w));
        *(float4*)(xs + row * 68 + col) = r;
    }
    if (tid < 64) {
        int node = base + tid;
        if (node < n) {
            g_pos4[node] = make_float4(pos[(size_t)node * 3 + 0],
                                       pos[(size_t)node * 3 + 1],
                                       pos[(size_t)node * 3 + 2], 0.f);
        }
    }
    __syncthreads();

    int r0 = (wid & 3) * 16;
    int nh = wid >> 2;
    int n0 = nh * 32;
    int rA = lane >> 2;
    int cb = 2 * (lane & 3);
    int rowg0 = base + r0 + rA;
    int rowg1 = rowg0 + 8;
    bool ok0 = rowg0 < n, ok1 = rowg1 < n;

    {
        float acc[4][4];
        #pragma unroll
        for (int nt = 0; nt < 4; nt++) {
            int col = n0 + nt * 8 + cb;
            float b0 = b_in[col], b1 = b_in[col + 1];
            acc[nt][0] = b0; acc[nt][1] = b1; acc[nt][2] = b0; acc[nt][3] = b1;
        }
        #pragma unroll
        for (int kt = 0; kt < 8; kt++) {
            int cA = kt * 8 + (lane & 3);
            unsigned a[4];
            a[0] = __float_as_uint(xs[(r0 + rA) * 68 + cA]);
            a[1] = __float_as_uint(xs[(r0 + 8 + rA) * 68 + cA]);
            a[2] = __float_as_uint(xs[(r0 + rA) * 68 + cA + 4]);
            a[3] = __float_as_uint(xs[(r0 + 8 + rA) * 68 + cA + 4]);
            #pragma unroll
            for (int nt = 0; nt < 4; nt++) {
                float2 b = ((const float2*)g_fWin)[(kt * 8 + nh * 4 + nt) * 32 + lane];
                MMA_TF32(acc[nt], a, __float_as_uint(b.x), __float_as_uint(b.y));
            }
        }
        #pragma unroll
        for (int nt = 0; nt < 4; nt++) {
            int col = n0 + nt * 8 + cb;
            hs[(r0 + rA) * 68 + col]       = __uint_as_float(f2tf32(fmaxf(acc[nt][0], 0.f)));
            hs[(r0 + rA) * 68 + col + 1]   = __uint_as_float(f2tf32(fmaxf(acc[nt][1], 0.f)));
            hs[(r0 + 8 + rA) * 68 + col]     = __uint_as_float(f2tf32(fmaxf(acc[nt][2], 0.f)));
            hs[(r0 + 8 + rA) * 68 + col + 1] = __uint_as_float(f2tf32(fmaxf(acc[nt][3], 0.f)));
        }
    }
    __syncthreads();

    {
        float acc[4][4];
        #pragma unroll
        for (int nt = 0; nt < 4; nt++)
            #pragma unroll
            for (int q = 0; q < 4; q++) acc[nt][q] = 0.f;
        #pragma unroll
        for (int kt = 0; kt < 8; kt++) {
            int cA = kt * 8 + (lane & 3);
            unsigned a[4];
            a[0] = __float_as_uint(hs[(r0 + rA) * 68 + cA]);
            a[1] = __float_as_uint(hs[(r0 + 8 + rA) * 68 + cA]);
            a[2] = __float_as_uint(hs[(r0 + rA) * 68 + cA + 4]);
            a[3] = __float_as_uint(hs[(r0 + 8 + rA) * 68 + cA + 4]);
            #pragma unroll
            for (int nt = 0; nt < 4; nt++) {
                float2 b = ((const float2*)g_fWlin)[(kt * 8 + nh * 4 + nt) * 32 + lane];
                MMA_TF32(acc[nt], a, __float_as_uint(b.x), __float_as_uint(b.y));
            }
        }
        #pragma unroll
        for (int nt = 0; nt < 4; nt++) {
            int col = n0 + nt * 8 + cb;
            vs[(r0 + rA) * 68 + col]         = acc[nt][0];
            vs[(r0 + rA) * 68 + col + 1]     = acc[nt][1];
            vs[(r0 + 8 + rA) * 68 + col]     = acc[nt][2];
            vs[(r0 + 8 + rA) * 68 + col + 1] = acc[nt][3];
            if (ok0) *(float2*)(g_v + (size_t)rowg0 * C + col) = make_float2(acc[nt][0], acc[nt][1]);
            if (ok1) *(float2*)(g_v + (size_t)rowg1 * C + col) = make_float2(acc[nt][2], acc[nt][3]);
        }
    }
    {
        float aq[4][4], ak[4][4];
        #pragma unroll
        for (int nt = 0; nt < 4; nt++)
            #pragma unroll
            for (int q = 0; q < 4; q++) { aq[nt][q] = 0.f; ak[nt][q] = 0.f; }
        #pragma unroll
        for (int kt = 0; kt < 8; kt++) {
            int cA = kt * 8 + (lane & 3);
            unsigned a[4];
            a[0] = __float_as_uint(hs[(r0 + rA) * 68 + cA]);
            a[1] = __float_as_uint(hs[(r0 + 8 + rA) * 68 + cA]);
            a[2] = __float_as_uint(hs[(r0 + rA) * 68 + cA + 4]);
            a[3] = __float_as_uint(hs[(r0 + 8 + rA) * 68 + cA + 4]);
            #pragma unroll
            for (int nt = 0; nt < 4; nt++) {
                float2 bq = ((const float2*)g_fMq)[(kt * 8 + nh * 4 + nt) * 32 + lane];
                float2 bk = ((const float2*)g_fMk)[(kt * 8 + nh * 4 + nt) * 32 + lane];
                MMA_TF32(aq[nt], a, __float_as_uint(bq.x), __float_as_uint(bq.y));
                MMA_TF32(ak[nt], a, __float_as_uint(bk.x), __float_as_uint(bk.y));
            }
        }
        #pragma unroll
        for (int nt = 0; nt < 4; nt++) {
            int col = n0 + nt * 8 + cb;
            float ba0 = att_b1[col], ba1 = att_b1[col + 1];
            xs[(r0 + rA) * 68 + col]       = __uint_as_float(f2tf32(fmaxf(aq[nt][0] - ak[nt][0] + ba0, 0.f)));
            xs[(r0 + rA) * 68 + col + 1]   = __uint_as_float(f2tf32(fmaxf(aq[nt][1] - ak[nt][1] + ba1, 0.f)));
            xs[(r0 + 8 + rA) * 68 + col]     = __uint_as_float(f2tf32(fmaxf(aq[nt][2] - ak[nt][2] + ba0, 0.f)));
            xs[(r0 + 8 + rA) * 68 + col + 1] = __uint_as_float(f2tf32(fmaxf(aq[nt][3] - ak[nt][3] + ba1, 0.f)));
            if (ok0) {
                *(float2*)(g_Q1 + (size_t)rowg0 * C + col) = make_float2(aq[nt][0], aq[nt][1]);
                *(float2*)(g_K1 + (size_t)rowg0 * C + col) = make_float2(ak[nt][0], ak[nt][1]);
            }
            if (ok1) {
                *(float2*)(g_Q1 + (size_t)rowg1 * C + col) = make_float2(aq[nt][2], aq[nt][3]);
                *(float2*)(g_K1 + (size_t)rowg1 * C + col) = make_float2(ak[nt][2], ak[nt][3]);
            }
        }
    }
    __syncthreads();

    {
        float acc[4][4];
        #pragma unroll
        for (int nt = 0; nt < 4; nt++) {
            int col = n0 + nt * 8 + cb;
            float b0 = att_b2[col], b1 = att_b2[col + 1];
            acc[nt][0] = b0; acc[nt][1] = b1; acc[nt][2] = b0; acc[nt][3] = b1;
        }
        #pragma unroll
        for (int kt = 0; kt < 8; kt++) {
            int cA = kt * 8 + (lane & 3);
            unsigned a[4];
            a[0] = __float_as_uint(xs[(r0 + rA) * 68 + cA]);
            a[1] = __float_as_uint(xs[(r0 + 8 + rA) * 68 + cA]);
            a[2] = __float_as_uint(xs[(r0 + rA) * 68 + cA + 4]);
            a[3] = __float_as_uint(xs[(r0 + 8 + rA) * 68 + cA + 4]);
            #pragma unroll
            for (int nt = 0; nt < 4; nt++) {
                float2 b = ((const float2*)g_fW2a)[(kt * 8 + nh * 4 + nt) * 32 + lane];
                MMA_TF32(acc[nt], a, __float_as_uint(b.x), __float_as_uint(b.y));
            }
        }
        #pragma unroll
        for (int nt = 0; nt < 4; nt++) {
            int col = n0 + nt * 8 + cb;
            float d0 = g_delta0[col], d1 = g_delta0[col + 1];
            float e0 = __expf(fmaxf(acc[nt][0], 0.f));
            float e1 = __expf(fmaxf(acc[nt][1], 0.f));
            float e2 = __expf(fmaxf(acc[nt][2], 0.f));
            float e3 = __expf(fmaxf(acc[nt][3], 0.f));
            if (ok0) {
                float v0 = vs[(r0 + rA) * 68 + col];
                float v1 = vs[(r0 + rA) * 68 + col + 1];
                *(float2*)(g_den + (size_t)rowg0 * C + col) = make_float2(e0, e1);
                *(float2*)(g_num + (size_t)rowg0 * C + col) = make_float2(e0 * (v0 + d0), e1 * (v1 + d1));
            }
            if (ok1) {
                float v2 = vs[(r0 + 8 + rA) * 68 + col];
                float v3 = vs[(r0 + 8 + rA) * 68 + col + 1];
                *(float2*)(g_den + (size_t)rowg1 * C + col) = make_float2(e2, e3);
                *(float2*)(g_num + (size_t)rowg1 * C + col) = make_float2(e2 * (v2 + d0), e3 * (v3 + d1));
            }
        }
    }
}

// ---------------- K2: edge kernel — fp16 MMA + ldmatrix + pos-delta on the fly --
// smem layout (bytes):
//   [0, 9216)        hidA16  64 rows x 72 halves
//   [9216, 18432)    hidP16
//   [18432, 35840)   exA     64 x 68 fp32
//   [35840, 53248)   dlP
//   [53248, 53760)   seB [2][64]
//   [53760, 54272)   deB [2][64]
__global__ void __launch_bounds__(256, 3)
edge_kernel(const int* __restrict__ src, const int* __restrict__ dst,
            const float* __restrict__ att_b1, const float* __restrict__ pos_b1,
            const float* __restrict__ pos_w1,
            const float* __restrict__ att_b2, const float* __restrict__ pos_b2,
            int E)
{
    extern __shared__ char smE[];
    __half* hidA16 = (__half*)smE;
    __half* hidP16 = (__half*)(smE + 9216);
    float*  exA    = (float*)(smE + 18432);
    float*  dlP    = (float*)(smE + 35840);
    int*    seB    = (int*)(smE + 53248);
    int*    deB    = (int*)(smE + 53760);

    int tid  = threadIdx.x;
    int lane = tid & 31;
    int wid  = tid >> 5;
    bool isA = (wid < 4);
    int sub  = wid & 3;
    int nhE  = sub & 1;
    int n0b  = nhE * 32;
    int mp   = sub >> 1;
    int r0m  = mp * 16;
    int r1m  = (mp + 2) * 16;

    const float* b2 = isA ? att_b2 : pos_b2;
    __half* hid = isA ? hidA16 : hidP16;
    float*  res = isA ? exA    : dlP;

    // preload fp16 B fragments (reg-resident): 32 regs
    uint2 bB[4][4];
    {
        const uint2* hw = isA ? g_hW2a : g_hW2p;
        #pragma unroll
        for (int kt = 0; kt < 4; kt++)
            #pragma unroll
            for (int nt = 0; nt < 4; nt++)
                bB[kt][nt] = hw[((kt * 8) + nhE * 4 + nt) * 32 + lane];
    }
    float bias0[4], bias1[4];
    #pragma unroll
    for (int nt = 0; nt < 4; nt++) {
        int col = n0b + nt * 8 + 2 * (lane & 3);
        bias0[nt] = b2[col];
        bias1[nt] = b2[col + 1];
    }

    // gather/scatter role: 16-lane group owns col slice js for edges {slot+16k}
    int slot = tid >> 4;
    int js   = (tid & 15) << 2;     // fp32 col index
    float4 ba1 = *(const float4*)(att_b1 + js);
    float4 bp1 = *(const float4*)(pos_b1 + js);
    // per-thread pos_w1 columns for the 4 owned channels
    float4 pwx, pwy, pwz;
    {
        float3 w0 = *(const float3*)(pos_w1 + (js + 0) * 3);
        float3 w1 = *(const float3*)(pos_w1 + (js + 1) * 3);
        float3 w2 = *(const float3*)(pos_w1 + (js + 2) * 3);
        float3 w3 = *(const float3*)(pos_w1 + (js + 3) * 3);
        pwx = make_float4(w0.x, w1.x, w2.x, w3.x);
        pwy = make_float4(w0.y, w1.y, w2.y, w3.y);
        pwz = make_float4(w0.z, w1.z, w2.z, w3.z);
    }

    // ldmatrix source addresses (shared-space u32)
    uint32_t hidBase;
    asm("{ .reg .u64 t; cvta.to.shared.u64 t, %1; cvt.u32.u64 %0, t; }"
        : "=r"(hidBase) : "l"(hid));
    uint32_t aAddr0 = hidBase + (uint32_t)(((r0m + (lane & 15)) * 72 + ((lane >> 4) << 3)) * 2);
    uint32_t aAddr1 = hidBase + (uint32_t)(((r1m + (lane & 15)) * 72 + ((lane >> 4) << 3)) * 2);

    int sPrev[4], dPrev[4];
    #pragma unroll
    for (int k = 0; k < 4; k++) dPrev[k] = -1;

    int ntiles = (E + 63) >> 6;

    {
        int base = blockIdx.x << 6;
        if (tid < 64) {
            int e = base + tid;
            seB[tid] = (e < E) ? src[e] : 0;
        } else if (tid < 128) {
            int e = base + tid - 64;
            deB[tid - 64] = (e < E) ? dst[e] : -1;
        }
    }
    __syncthreads();

    int it = 0;
    for (int tile = blockIdx.x; tile < ntiles; tile += gridDim.x, it ^= 1) {
        // ===== PHASE A: scatter(prev) + gather(cur) + idx prefetch(next) =====
        #pragma unroll
        for (int k = 0; k < 4; k++) {
            int d = dPrev[k];
            if (d >= 0) {
                int e = slot + 16 * k;
                float4 ex = *(const float4*)(exA + e * 68 + js);
                float4 dl = *(const float4*)(dlP + e * 68 + js);
                float4 vv = *(const float4*)(g_v + (size_t)sPrev[k] * C + js);
                float4 nv;
                nv.x = ex.x * (vv.x + dl.x);
                nv.y = ex.y * (vv.y + dl.y);
                nv.z = ex.z * (vv.z + dl.z);
                nv.w = ex.w * (vv.w + dl.w);
                RED_V4(g_num + (size_t)d * C + js, nv);
                RED_V4(g_den + (size_t)d * C + js, ex);
            }
        }
        #pragma unroll
        for (int k = 0; k < 4; k++) {
            int e = slot + 16 * k;
            int s = seB[it * 64 + e];
            int d = deB[it * 64 + e];
            sPrev[k] = s;
            dPrev[k] = d;
            int dc = d < 0 ? 0 : d;
            float4 qv = *(const float4*)(g_Q1 + (size_t)dc * C + js);
            float4 kv = *(const float4*)(g_K1 + (size_t)s  * C + js);
            float4 p4d = g_pos4[dc];      // broadcast within group
            float4 p4s = g_pos4[s];
            float dpx = p4d.x - p4s.x, dpy = p4d.y - p4s.y, dpz = p4d.z - p4s.z;
            uint2 ua, up;
            if (d >= 0) {
                ua.x = pack_h2(fmaxf(qv.x - kv.x + ba1.x, 0.f), fmaxf(qv.y - kv.y + ba1.y, 0.f));
                ua.y = pack_h2(fmaxf(qv.z - kv.z + ba1.z, 0.f), fmaxf(qv.w - kv.w + ba1.w, 0.f));
                float r0p = fmaf(dpx, pwx.x, fmaf(dpy, pwy.x, fmaf(dpz, pwz.x, bp1.x)));
                float r1p = fmaf(dpx, pwx.y, fmaf(dpy, pwy.y, fmaf(dpz, pwz.y, bp1.y)));
                float r2p = fmaf(dpx, pwx.z, fmaf(dpy, pwy.z, fmaf(dpz, pwz.z, bp1.z)));
                float r3p = fmaf(dpx, pwx.w, fmaf(dpy, pwy.w, fmaf(dpz, pwz.w, bp1.w)));
                up.x = pack_h2(fmaxf(r0p, 0.f), fmaxf(r1p, 0.f));
                up.y = pack_h2(fmaxf(r2p, 0.f), fmaxf(r3p, 0.f));
            } else {
                ua = make_uint2(0u, 0u);
                up = ua;
            }
            *(uint2*)(hidA16 + e * 72 + js) = ua;
            *(uint2*)(hidP16 + e * 72 + js) = up;
        }
        {
            int ntile = tile + gridDim.x;
            if (ntile < ntiles) {
                int base = ntile << 6;
                int ib = (it ^ 1) * 64;
                if (tid < 64) {
                    int e = base + tid;
                    seB[ib + tid] = (e < E) ? src[e] : 0;
                } else if (tid < 128) {
                    int e = base + tid - 64;
                    deB[ib + tid - 64] = (e < E) ? dst[e] : -1;
                }
            }
        }
        __syncthreads();

        // ===== PHASE B: fp16 m16n8k16 MMA (ldmatrix A) + epilogue =====
        float acc[2][4][4];
        #pragma unroll
        for (int s2 = 0; s2 < 2; s2++)
            #pragma unroll
            for (int nt = 0; nt < 4; nt++) {
                acc[s2][nt][0] = bias0[nt];
                acc[s2][nt][1] = bias1[nt];
                acc[s2][nt][2] = bias0[nt];
                acc[s2][nt][3] = bias1[nt];
            }
        #pragma unroll
        for (int kt = 0; kt < 4; kt++) {
            unsigned a0[4], a1[4];
            ldsm_x4(a0[0], a0[1], a0[2], a0[3], aAddr0 + kt * 32);
            ldsm_x4(a1[0], a1[1], a1[2], a1[3], aAddr1 + kt * 32);
            #pragma unroll
            for (int nt = 0; nt < 4; nt++) {
                MMA_F16(acc[0][nt], a0, bB[kt][nt].x, bB[kt][nt].y);
                MMA_F16(acc[1][nt], a1, bB[kt][nt].x, bB[kt][nt].y);
            }
        }
        {
            int rA = lane >> 2;
            int cbv = 2 * (lane & 3);
            #pragma unroll
            for (int s2 = 0; s2 < 2; s2++) {
                int rb = (s2 ? r1m : r0m) + rA;
                #pragma unroll
                for (int nt = 0; nt < 4; nt++) {
                    int col = n0b + nt * 8 + cbv;
                    float v0, v1, v2, v3;
                    if (isA) {
                        v0 = __expf(fmaxf(acc[s2][nt][0], 0.f));
                        v1 = __expf(fmaxf(acc[s2][nt][1], 0.f));
                        v2 = __expf(fmaxf(acc[s2][nt][2], 0.f));
                        v3 = __expf(fmaxf(acc[s2][nt][3], 0.f));
                    } else {
                        v0 = fmaxf(acc[s2][nt][0], 0.f);
                        v1 = fmaxf(acc[s2][nt][1], 0.f);
                        v2 = fmaxf(acc[s2][nt][2], 0.f);
                        v3 = fmaxf(acc[s2][nt][3], 0.f);
                    }
                    *(float2*)(res + rb * 68 + col)       = make_float2(v0, v1);
                    *(float2*)(res + (rb + 8) * 68 + col) = make_float2(v2, v3);
                }
            }
        }
        __syncthreads();
    }

    // ===== pipeline drain: scatter of the final tile =====
    #pragma unroll
    for (int k = 0; k < 4; k++) {
        int d = dPrev[k];
        if (d >= 0) {
            int e = slot + 16 * k;
            float4 ex = *(const float4*)(exA + e * 68 + js);
            float4 dl = *(const float4*)(dlP + e * 68 + js);
            float4 vv = *(const float4*)(g_v + (size_t)sPrev[k] * C + js);
            float4 nv;
            nv.x = ex.x * (vv.x + dl.x);
            nv.y = ex.y * (vv.y + dl.y);
            nv.z = ex.z * (vv.z + dl.z);
            nv.w = ex.w * (vv.w + dl.w);
            RED_V4(g_num + (size_t)d * C + js, nv);
            RED_V4(g_den + (size_t)d * C + js, ex);
        }
    }
}

// ---------------- K3: out kernel — tf32 MMA over 64-node tiles ------------------
__global__ void __launch_bounds__(256)
out_kernel(const float* __restrict__ b_out, float* __restrict__ out, int n)
{
    __shared__ float rs[64 * 68];
    int tid  = threadIdx.x;
    int lane = tid & 31;
    int wid  = tid >> 5;
    int base = blockIdx.x * 64;

    for (int t = tid; t < 1024; t += 256) {
        int row = t >> 4;
        int col = (t & 15) * 4;
        int node = base + row;
        float4 r = make_float4(0.f, 0.f, 0.f, 0.f);
        if (node < n) {
            float4 nu = *(const float4*)(g_num + (size_t)node * C + col);
            float4 de = *(const float4*)(g_den + (size_t)node * C + col);
            r.x = __uint_as_float(f2tf32(nu.x / (de.x + 1e-16f)));
            r.y = __uint_as_float(f2tf32(nu.y / (de.y + 1e-16f)));
            r.z = __uint_as_float(f2tf32(nu.z / (de.z + 1e-16f)));
            r.w = __uint_as_float(f2tf32(nu.w / (de.w + 1e-16f)));
        }
        *(float4*)(rs + row * 68 + col) = r;
    }
    __syncthreads();

    int r0 = (wid & 3) * 16;
    int nh = wid >> 2;
    int n0 = nh * 32;
    int rA = lane >> 2;
    int cb = 2 * (lane & 3);
    int rowg0 = base + r0 + rA;
    int rowg1 = rowg0 + 8;

    float acc[4][4];
    #pragma unroll
    for (int nt = 0; nt < 4; nt++) {
        int col = n0 + nt * 8 + cb;
        float b0 = b_out[col], b1 = b_out[col + 1];
        acc[nt][0] = b0; acc[nt][1] = b1; acc[nt][2] = b0; acc[nt][3] = b1;
    }
    #pragma unroll
    for (int kt = 0; kt < 8; kt++) {
        int cA = kt * 8 + (lane & 3);
        unsigned a[4];
        a[0] = __float_as_uint(rs[(r0 + rA) * 68 + cA]);
        a[1] = __float_as_uint(rs[(r0 + 8 + rA) * 68 + cA]);
        a[2] = __float_as_uint(rs[(r0 + rA) * 68 + cA + 4]);
        a[3] = __float_as_uint(rs[(r0 + 8 + rA) * 68 + cA + 4]);
        #pragma unroll
        for (int nt = 0; nt < 4; nt++) {
            float2 b = ((const float2*)g_fWout)[(kt * 8 + nh * 4 + nt) * 32 + lane];
            MMA_TF32(acc[nt], a, __float_as_uint(b.x), __float_as_uint(b.y));
        }
    }
    #pragma unroll
    for (int nt = 0; nt < 4; nt++) {
        int col = n0 + nt * 8 + cb;
        if (rowg0 < n)
            *(float2*)(out + (size_t)rowg0 * C + col) =
                make_float2(fmaxf(acc[nt][0], 0.f), fmaxf(acc[nt][1], 0.f));
        if (rowg1 < n)
            *(float2*)(out + (size_t)rowg1 * C + col) =
                make_float2(fmaxf(acc[nt][2], 0.f), fmaxf(acc[nt][3], 0.f));
    }
}

// ---------------- launch --------------------------------------------------------
extern "C" void kernel_launch(void* const* d_in, const int* in_sizes, int n_in,
                              void* d_out, int out_size)
{
    const float* x      = (const float*)d_in[0];
    const float* pos    = (const float*)d_in[1];
    const int*   ei     = (const int*)  d_in[2];
    const float* W_in   = (const float*)d_in[3];
    const float* b_in   = (const float*)d_in[4];
    const float* W_out  = (const float*)d_in[5];
    const float* b_out  = (const float*)d_in[6];
    const float* W_lin  = (const float*)d_in[7];
    const float* W_src  = (const float*)d_in[8];
    const float* W_dst  = (const float*)d_in[9];
    const float* pos_w1 = (const float*)d_in[10];
    const float* pos_b1 = (const float*)d_in[11];
    const float* pos_w2 = (const float*)d_in[12];
    const float* pos_b2 = (const float*)d_in[13];
    const float* att_w1 = (const float*)d_in[14];
    const float* att_b1 = (const float*)d_in[15];
    const float* att_w2 = (const float*)d_in[16];
    const float* att_b2 = (const float*)d_in[17];

    int n = in_sizes[0] / C;
    int E = in_sizes[2] / 2;
    const int* srcArr = ei;
    const int* dstArr = ei + E;

    size_t smemNode = (size_t)(3 * 64 * 68) * sizeof(float);   // 52224
    size_t smemEdge = 54272;
    cudaFuncSetAttribute(node_kernel, cudaFuncAttributeMaxDynamicSharedMemorySize, (int)smemNode);
    cudaFuncSetAttribute(edge_kernel, cudaFuncAttributeMaxDynamicSharedMemorySize, (int)smemEdge);

    int tilesN = (n + 63) / 64;

    prep_kernel<<<1, 256>>>(att_w1, W_dst, W_src, W_in, W_lin, att_w2, pos_w2, W_out,
                            pos_b1, pos_b2);
    node_kernel<<<tilesN, 256, smemNode>>>(x, pos, b_in, att_b1, att_b2, n);
    spacer_kernel<<<1, 32>>>();   // keeps edge_kernel at launch #4 (ncu capture slot)
    edge_kernel<<<444, 256, smemEdge>>>(srcArr, dstArr, att_b1, pos_b1, pos_w1,
                                        att_b2, pos_b2, E);
    out_kernel<<<tilesN, 256>>>(b_out, (float*)d_out, n);
}

// round 12
// speedup vs baseline: 1.3604x; 1.0195x over previous
#include <cuda_runtime.h>
#include <cuda_fp16.h>
#include <cstdint>

#define C 64
#define MAXN 50000
#define MAXE 800000

// ---------------- device scratch (static: no allocation allowed) ----------------
__device__ float  g_v[MAXN * C];
__device__ __half g_hQ1[MAXN * C];
__device__ __half g_hK1[MAXN * C];
__device__ float4 g_pos4[MAXN];
__device__ float  g_num[MAXN * C];
__device__ float  g_den[MAXN * C];
__device__ float g_Mq_t[C * C];
__device__ float g_Mk_t[C * C];
__device__ float g_Win_t[C * C];
__device__ float g_Wlin_t[C * C];
__device__ float g_w2a_t[C * C];
__device__ float g_w2p_t[C * C];
__device__ float g_Wout_t[C * C];
__device__ float g_delta0[C];
__device__ float g_fWin[4096];
__device__ float g_fWlin[4096];
__device__ float g_fMq[4096];
__device__ float g_fMk[4096];
__device__ float g_fW2a[4096];
__device__ float g_fWout[4096];
// fp16 B fragments for edge MLP-2 GEMMs: [(kt*8+nt)*32+lane] -> uint2 {b0,b1}
__device__ uint2 g_hW2a[1024];
__device__ uint2 g_hW2p[1024];

__device__ __forceinline__ unsigned f2tf32(float f) {
    unsigned r;
    asm("cvt.rna.tf32.f32 %0, %1;" : "=r"(r) : "f"(f));
    return r;
}
__device__ __forceinline__ unsigned pack_h2(float a, float b) {
    __half2 h = __floats2half2_rn(a, b);
    return *reinterpret_cast<unsigned*>(&h);
}

#define MMA_TF32(d, a, b0, b1)                                               \
    asm volatile("mma.sync.aligned.m16n8k8.row.col.f32.tf32.tf32.f32 "       \
                 "{%0,%1,%2,%3}, {%4,%5,%6,%7}, {%8,%9}, {%0,%1,%2,%3};"     \
                 : "+f"(d[0]), "+f"(d[1]), "+f"(d[2]), "+f"(d[3])            \
                 : "r"(a[0]), "r"(a[1]), "r"(a[2]), "r"(a[3]),               \
                   "r"(b0), "r"(b1))

#define MMA_F16(d, a, b0, b1)                                                \
    asm volatile("mma.sync.aligned.m16n8k16.row.col.f32.f16.f16.f32 "        \
                 "{%0,%1,%2,%3}, {%4,%5,%6,%7}, {%8,%9}, {%0,%1,%2,%3};"     \
                 : "+f"(d[0]), "+f"(d[1]), "+f"(d[2]), "+f"(d[3])            \
                 : "r"(a[0]), "r"(a[1]), "r"(a[2]), "r"(a[3]),               \
                   "r"(b0), "r"(b1))

#define RED_V4(ptr, v)                                                       \
    asm volatile("red.global.add.v4.f32 [%0], {%1,%2,%3,%4};"                \
                 :: "l"(ptr), "f"((v).x), "f"((v).y), "f"((v).z), "f"((v).w) \
                 : "memory")

__device__ __forceinline__ void ldsm_x4(unsigned& r0, unsigned& r1,
                                        unsigned& r2, unsigned& r3, unsigned addr) {
    asm volatile("ldmatrix.sync.aligned.m8n8.x4.shared.b16 {%0,%1,%2,%3}, [%4];"
                 : "=r"(r0), "=r"(r1), "=r"(r2), "=r"(r3) : "r"(addr));
}

// ---------------- K0: weight prep ------------------------------------------------
__global__ void prep_kernel(const float* __restrict__ att_w1,
                            const float* __restrict__ W_dst,
                            const float* __restrict__ W_src,
                            const float* __restrict__ W_in,
                            const float* __restrict__ W_lin,
                            const float* __restrict__ att_w2,
                            const float* __restrict__ pos_w2,
                            const float* __restrict__ W_out,
                            const float* __restrict__ pos_b1,
                            const float* __restrict__ pos_b2)
{
    __shared__ float s_a[C * C];
    __shared__ float s_d[C * C];
    __shared__ float s_s[C * C];
    int tid = threadIdx.x;
    for (int t = tid; t < C * C; t += blockDim.x) {
        s_a[t] = att_w1[t];
        s_d[t] = W_dst[t];
        s_s[t] = W_src[t];
    }
    __syncthreads();
    for (int idx = tid; idx < C * C; idx += blockDim.x) {
        int t = idx >> 6, j = idx & 63;
        float aq = 0.f, ak = 0.f;
        #pragma unroll 8
        for (int u = 0; u < C; u++) {
            float a = s_a[t * C + u];
            aq = fmaf(a, s_d[u * C + j], aq);
            ak = fmaf(a, s_s[u * C + j], ak);
        }
        g_Mq_t[j * C + t] = aq;
        g_Mk_t[j * C + t] = ak;
    }
    for (int idx = tid; idx < C * C; idx += blockDim.x) {
        int cc = idx >> 6, j = idx & 63;
        g_Win_t[j * C + cc]  = W_in[idx];
        g_Wlin_t[j * C + cc] = W_lin[idx];
        g_w2a_t[j * C + cc]  = att_w2[idx];
        g_w2p_t[j * C + cc]  = pos_w2[idx];
        g_Wout_t[j * C + cc] = W_out[idx];
    }
    if (tid < C) {
        float acc = pos_b2[tid];
        #pragma unroll 8
        for (int j = 0; j < C; j++)
            acc = fmaf(fmaxf(pos_b1[j], 0.f), pos_w2[tid * C + j], acc);
        g_delta0[tid] = fmaxf(acc, 0.f);
    }
    __syncthreads();
    for (int t = tid; t < 2048; t += blockDim.x) {
        int kt   = t >> 8;
        int nt   = (t >> 5) & 7;
        int lane = t & 31;
        int kr = kt * 8 + (lane & 3);
        int nc = nt * 8 + (lane >> 2);
        int lo = kr * 64 + nc, hi = (kr + 4) * 64 + nc;
        ((float2*)g_fWin)[t]  = make_float2(__uint_as_float(f2tf32(g_Win_t[lo])),
                                            __uint_as_float(f2tf32(g_Win_t[hi])));
        ((float2*)g_fWlin)[t] = make_float2(__uint_as_float(f2tf32(g_Wlin_t[lo])),
                                            __uint_as_float(f2tf32(g_Wlin_t[hi])));
        ((float2*)g_fMq)[t]   = make_float2(__uint_as_float(f2tf32(g_Mq_t[lo])),
                                            __uint_as_float(f2tf32(g_Mq_t[hi])));
        ((float2*)g_fMk)[t]   = make_float2(__uint_as_float(f2tf32(g_Mk_t[lo])),
                                            __uint_as_float(f2tf32(g_Mk_t[hi])));
        ((float2*)g_fW2a)[t]  = make_float2(__uint_as_float(f2tf32(g_w2a_t[lo])),
                                            __uint_as_float(f2tf32(g_w2a_t[hi])));
        ((float2*)g_fWout)[t] = make_float2(__uint_as_float(f2tf32(g_Wout_t[lo])),
                                            __uint_as_float(f2tf32(g_Wout_t[hi])));
    }
    // fp16 B fragments for edge kernel (m16n8k16)
    for (int t = tid; t < 1024; t += blockDim.x) {
        int kt   = t >> 8;
        int nt   = (t >> 5) & 7;
        int lane = t & 31;
        int tig = lane & 3, gid = lane >> 2;
        int n  = nt * 8 + gid;
        int k0 = kt * 16 + tig * 2;
        uint2 ua, up;
        ua.x = pack_h2(g_w2a_t[k0 * 64 + n],       g_w2a_t[(k0 + 1) * 64 + n]);
        ua.y = pack_h2(g_w2a_t[(k0 + 8) * 64 + n], g_w2a_t[(k0 + 9) * 64 + n]);
        up.x = pack_h2(g_w2p_t[k0 * 64 + n],       g_w2p_t[(k0 + 1) * 64 + n]);
        up.y = pack_h2(g_w2p_t[(k0 + 8) * 64 + n], g_w2p_t[(k0 + 9) * 64 + n]);
        g_hW2a[t] = ua;
        g_hW2p[t] = up;
    }
}

// ---------------- dummy (instrumentation spacer so ncu window hits edge_kernel) --
__global__ void spacer_kernel() {}

// ---------------- K1: node kernel — 4 fused tf32 GEMMs over 64-node tiles -------
__global__ void __launch_bounds__(256)
node_kernel(const float* __restrict__ x,
            const float* __restrict__ pos,
            const float* __restrict__ b_in,
            const float* __restrict__ att_b1,
            const float* __restrict__ att_b2,
            int n)
{
    extern __shared__ float sm[];
    float* xs = sm;
    float* hs = sm + 4352;
    float* vs = sm + 8704;
    int tid  = threadIdx.x;
    int lane = tid & 31;
    int wid  = tid >> 5;
    int base = blockIdx.x * 64;

    for (int t = tid; t < 1024; t += 256) {
        int row = t >> 4;
        int col = (t & 15) * 4;
        int node = base + row;
        float4 v4 = make_float4(0.f, 0.f, 0.f, 0.f);
        if (node < n) v4 = *(const float4*)(x + (size_t)node * C + col);
        float4 r;
        r.x = __uint_as_float(f2tf32(v4.x));
        r.y = __uint_as_float(f2tf32(v4.y));
        r.z = __uint_as_float(f2tf32(v4.z));
        r.w = __uint_as_float(f2tf32(v4.w));
        *(float4*)(xs + row * 68 + col) = r;
    }
    if (tid < 64) {
        int node = base + tid;
        if (node < n) {
            g_pos4[node] = make_float4(pos[(size_t)node * 3 + 0],
                                       pos[(size_t)node * 3 + 1],
                                       pos[(size_t)node * 3 + 2], 0.f);
        }
    }
    __syncthreads();

    int r0 = (wid & 3) * 16;
    int nh = wid >> 2;
    int n0 = nh * 32;
    int rA = lane >> 2;
    int cb = 2 * (lane & 3);
    int rowg0 = base + r0 + rA;
    int rowg1 = rowg0 + 8;
    bool ok0 = rowg0 < n, ok1 = rowg1 < n;

    {
        float acc[4][4];
        #pragma unroll
        for (int nt = 0; nt < 4; nt++) {
            int col = n0 + nt * 8 + cb;
            float b0 = b_in[col], b1 = b_in[col + 1];
            acc[nt][0] = b0; acc[nt][1] = b1; acc[nt][2] = b0; acc[nt][3] = b1;
        }
        #pragma unroll
        for (int kt = 0; kt < 8; kt++) {
            int cA = kt * 8 + (lane & 3);
            unsigned a[4];
            a[0] = __float_as_uint(xs[(r0 + rA) * 68 + cA]);
            a[1] = __float_as_uint(xs[(r0 + 8 + rA) * 68 + cA]);
            a[2] = __float_as_uint(xs[(r0 + rA) * 68 + cA + 4]);
            a[3] = __float_as_uint(xs[(r0 + 8 + rA) * 68 + cA + 4]);
            #pragma unroll
            for (int nt = 0; nt < 4; nt++) {
                float2 b = ((const float2*)g_fWin)[(kt * 8 + nh * 4 + nt) * 32 + lane];
                MMA_TF32(acc[nt], a, __float_as_uint(b.x), __float_as_uint(b.y));
            }
        }
        #pragma unroll
        for (int nt = 0; nt < 4; nt++) {
            int col = n0 + nt * 8 + cb;
            hs[(r0 + rA) * 68 + col]       = __uint_as_float(f2tf32(fmaxf(acc[nt][0], 0.f)));
            hs[(r0 + rA) * 68 + col + 1]   = __uint_as_float(f2tf32(fmaxf(acc[nt][1], 0.f)));
            hs[(r0 + 8 + rA) * 68 + col]     = __uint_as_float(f2tf32(fmaxf(acc[nt][2], 0.f)));
            hs[(r0 + 8 + rA) * 68 + col + 1] = __uint_as_float(f2tf32(fmaxf(acc[nt][3], 0.f)));
        }
    }
    __syncthreads();

    {
        float acc[4][4];
        #pragma unroll
        for (int nt = 0; nt < 4; nt++)
            #pragma unroll
            for (int q = 0; q < 4; q++) acc[nt][q] = 0.f;
        #pragma unroll
        for (int kt = 0; kt < 8; kt++) {
            int cA = kt * 8 + (lane & 3);
            unsigned a[4];
            a[0] = __float_as_uint(hs[(r0 + rA) * 68 + cA]);
            a[1] = __float_as_uint(hs[(r0 + 8 + rA) * 68 + cA]);
            a[2] = __float_as_uint(hs[(r0 + rA) * 68 + cA + 4]);
            a[3] = __float_as_uint(hs[(r0 + 8 + rA) * 68 + cA + 4]);
            #pragma unroll
            for (int nt = 0; nt < 4; nt++) {
                float2 b = ((const float2*)g_fWlin)[(kt * 8 + nh * 4 + nt) * 32 + lane];
                MMA_TF32(acc[nt], a, __float_as_uint(b.x), __float_as_uint(b.y));
            }
        }
        #pragma unroll
        for (int nt = 0; nt < 4; nt++) {
            int col = n0 + nt * 8 + cb;
            vs[(r0 + rA) * 68 + col]         = acc[nt][0];
            vs[(r0 + rA) * 68 + col + 1]     = acc[nt][1];
            vs[(r0 + 8 + rA) * 68 + col]     = acc[nt][2];
            vs[(r0 + 8 + rA) * 68 + col + 1] = acc[nt][3];
            if (ok0) *(float2*)(g_v + (size_t)rowg0 * C + col) = make_float2(acc[nt][0], acc[nt][1]);
            if (ok1) *(float2*)(g_v + (size_t)rowg1 * C + col) = make_float2(acc[nt][2], acc[nt][3]);
        }
    }
    {
        float aq[4][4], ak[4][4];
        #pragma unroll
        for (int nt = 0; nt < 4; nt++)
            #pragma unroll
            for (int q = 0; q < 4; q++) { aq[nt][q] = 0.f; ak[nt][q] = 0.f; }
        #pragma unroll
        for (int kt = 0; kt < 8; kt++) {
            int cA = kt * 8 + (lane & 3);
            unsigned a[4];
            a[0] = __float_as_uint(hs[(r0 + rA) * 68 + cA]);
            a[1] = __float_as_uint(hs[(r0 + 8 + rA) * 68 + cA]);
            a[2] = __float_as_uint(hs[(r0 + rA) * 68 + cA + 4]);
            a[3] = __float_as_uint(hs[(r0 + 8 + rA) * 68 + cA + 4]);
            #pragma unroll
            for (int nt = 0; nt < 4; nt++) {
                float2 bq = ((const float2*)g_fMq)[(kt * 8 + nh * 4 + nt) * 32 + lane];
                float2 bk = ((const float2*)g_fMk)[(kt * 8 + nh * 4 + nt) * 32 + lane];
                MMA_TF32(aq[nt], a, __float_as_uint(bq.x), __float_as_uint(bq.y));
                MMA_TF32(ak[nt], a, __float_as_uint(bk.x), __float_as_uint(bk.y));
            }
        }
        #pragma unroll
        for (int nt = 0; nt < 4; nt++) {
            int col = n0 + nt * 8 + cb;
            float ba0 = att_b1[col], ba1 = att_b1[col + 1];
            xs[(r0 + rA) * 68 + col]       = __uint_as_float(f2tf32(fmaxf(aq[nt][0] - ak[nt][0] + ba0, 0.f)));
            xs[(r0 + rA) * 68 + col + 1]   = __uint_as_float(f2tf32(fmaxf(aq[nt][1] - ak[nt][1] + ba1, 0.f)));
            xs[(r0 + 8 + rA) * 68 + col]     = __uint_as_float(f2tf32(fmaxf(aq[nt][2] - ak[nt][2] + ba0, 0.f)));
            xs[(r0 + 8 + rA) * 68 + col + 1] = __uint_as_float(f2tf32(fmaxf(aq[nt][3] - ak[nt][3] + ba1, 0.f)));
            if (ok0) {
                *(__half2*)(g_hQ1 + (size_t)rowg0 * C + col) = __floats2half2_rn(aq[nt][0], aq[nt][1]);
                *(__half2*)(g_hK1 + (size_t)rowg0 * C + col) = __floats2half2_rn(ak[nt][0], ak[nt][1]);
            }
            if (ok1) {
                *(__half2*)(g_hQ1 + (size_t)rowg1 * C + col) = __floats2half2_rn(aq[nt][2], aq[nt][3]);
                *(__half2*)(g_hK1 + (size_t)rowg1 * C + col) = __floats2half2_rn(ak[nt][2], ak[nt][3]);
            }
        }
    }
    __syncthreads();

    {
        float acc[4][4];
        #pragma unroll
        for (int nt = 0; nt < 4; nt++) {
            int col = n0 + nt * 8 + cb;
            float b0 = att_b2[col], b1 = att_b2[col + 1];
            acc[nt][0] = b0; acc[nt][1] = b1; acc[nt][2] = b0; acc[nt][3] = b1;
        }
        #pragma unroll
        for (int kt = 0; kt < 8; kt++) {
            int cA = kt * 8 + (lane & 3);
            unsigned a[4];
            a[0] = __float_as_uint(xs[(r0 + rA) * 68 + cA]);
            a[1] = __float_as_uint(xs[(r0 + 8 + rA) * 68 + cA]);
            a[2] = __float_as_uint(xs[(r0 + rA) * 68 + cA + 4]);
            a[3] = __float_as_uint(xs[(r0 + 8 + rA) * 68 + cA + 4]);
            #pragma unroll
            for (int nt = 0; nt < 4; nt++) {
                float2 b = ((const float2*)g_fW2a)[(kt * 8 + nh * 4 + nt) * 32 + lane];
                MMA_TF32(acc[nt], a, __float_as_uint(b.x), __float_as_uint(b.y));
            }
        }
        #pragma unroll
        for (int nt = 0; nt < 4; nt++) {
            int col = n0 + nt * 8 + cb;
            float d0 = g_delta0[col], d1 = g_delta0[col + 1];
            float e0 = __expf(fmaxf(acc[nt][0], 0.f));
            float e1 = __expf(fmaxf(acc[nt][1], 0.f));
            float e2 = __expf(fmaxf(acc[nt][2], 0.f));
            float e3 = __expf(fmaxf(acc[nt][3], 0.f));
            if (ok0) {
                float v0 = vs[(r0 + rA) * 68 + col];
                float v1 = vs[(r0 + rA) * 68 + col + 1];
                *(float2*)(g_den + (size_t)rowg0 * C + col) = make_float2(e0, e1);
                *(float2*)(g_num + (size_t)rowg0 * C + col) = make_float2(e0 * (v0 + d0), e1 * (v1 + d1));
            }
            if (ok1) {
                float v2 = vs[(r0 + 8 + rA) * 68 + col];
                float v3 = vs[(r0 + 8 + rA) * 68 + col + 1];
                *(float2*)(g_den + (size_t)rowg1 * C + col) = make_float2(e2, e3);
                *(float2*)(g_num + (size_t)rowg1 * C + col) = make_float2(e2 * (v2 + d0), e3 * (v3 + d1));
            }
        }
    }
}

// ---------------- K2: edge kernel — fp16 gather + fp16 MMA + ldmatrix -----------
// smem layout (bytes):
//   [0, 9216)        hidA16  64 rows x 72 halves
//   [9216, 18432)    hidP16
//   [18432, 35840)   exA     64 x 68 fp32
//   [35840, 53248)   dlP
//   [53248, 53760)   seB [2][64]
//   [53760, 54272)   deB [2][64]
__global__ void __launch_bounds__(256, 3)
edge_kernel(const int* __restrict__ src, const int* __restrict__ dst,
            const float* __restrict__ att_b1, const float* __restrict__ pos_b1,
            const float* __restrict__ pos_w1,
            const float* __restrict__ att_b2, const float* __restrict__ pos_b2,
            int E)
{
    extern __shared__ char smE[];
    __half* hidA16 = (__half*)smE;
    __half* hidP16 = (__half*)(smE + 9216);
    float*  exA    = (float*)(smE + 18432);
    float*  dlP    = (float*)(smE + 35840);
    int*    seB    = (int*)(smE + 53248);
    int*    deB    = (int*)(smE + 53760);

    int tid  = threadIdx.x;
    int lane = tid & 31;
    int wid  = tid >> 5;
    bool isA = (wid < 4);
    int sub  = wid & 3;
    int nhE  = sub & 1;
    int n0b  = nhE * 32;
    int mp   = sub >> 1;
    int r0m  = mp * 16;
    int r1m  = (mp + 2) * 16;

    const float* b2 = isA ? att_b2 : pos_b2;
    __half* hid = isA ? hidA16 : hidP16;
    float*  res = isA ? exA    : dlP;

    // preload fp16 B fragments (reg-resident): 32 regs
    uint2 bB[4][4];
    {
        const uint2* hw = isA ? g_hW2a : g_hW2p;
        #pragma unroll
        for (int kt = 0; kt < 4; kt++)
            #pragma unroll
            for (int nt = 0; nt < 4; nt++)
                bB[kt][nt] = hw[((kt * 8) + nhE * 4 + nt) * 32 + lane];
    }
    float bias0[4], bias1[4];
    #pragma unroll
    for (int nt = 0; nt < 4; nt++) {
        int col = n0b + nt * 8 + 2 * (lane & 3);
        bias0[nt] = b2[col];
        bias1[nt] = b2[col + 1];
    }

    // gather/scatter role: 16-lane group owns col slice js for edges {slot+16k}
    int slot = tid >> 4;
    int js   = (tid & 15) << 2;     // fp32 col index
    float4 ba1 = *(const float4*)(att_b1 + js);
    __half2 ba1h0 = __floats2half2_rn(ba1.x, ba1.y);
    __half2 ba1h1 = __floats2half2_rn(ba1.z, ba1.w);
    __half2 hzero = __floats2half2_rn(0.f, 0.f);
    float4 bp1 = *(const float4*)(pos_b1 + js);
    // per-thread pos_w1 columns for the 4 owned channels
    float4 pwx, pwy, pwz;
    {
        float3 w0 = *(const float3*)(pos_w1 + (js + 0) * 3);
        float3 w1 = *(const float3*)(pos_w1 + (js + 1) * 3);
        float3 w2 = *(const float3*)(pos_w1 + (js + 2) * 3);
        float3 w3 = *(const float3*)(pos_w1 + (js + 3) * 3);
        pwx = make_float4(w0.x, w1.x, w2.x, w3.x);
        pwy = make_float4(w0.y, w1.y, w2.y, w3.y);
        pwz = make_float4(w0.z, w1.z, w2.z, w3.z);
    }

    // ldmatrix source addresses (shared-space u32)
    uint32_t hidBase;
    asm("{ .reg .u64 t; cvta.to.shared.u64 t, %1; cvt.u32.u64 %0, t; }"
        : "=r"(hidBase) : "l"(hid));
    uint32_t aAddr0 = hidBase + (uint32_t)(((r0m + (lane & 15)) * 72 + ((lane >> 4) << 3)) * 2);
    uint32_t aAddr1 = hidBase + (uint32_t)(((r1m + (lane & 15)) * 72 + ((lane >> 4) << 3)) * 2);

    int sPrev[4], dPrev[4];
    #pragma unroll
    for (int k = 0; k < 4; k++) dPrev[k] = -1;

    int ntiles = (E + 63) >> 6;

    {
        int base = blockIdx.x << 6;
        if (tid < 64) {
            int e = base + tid;
            seB[tid] = (e < E) ? src[e] : 0;
        } else if (tid < 128) {
            int e = base + tid - 64;
            deB[tid - 64] = (e < E) ? dst[e] : -1;
        }
    }
    __syncthreads();

    int it = 0;
    for (int tile = blockIdx.x; tile < ntiles; tile += gridDim.x, it ^= 1) {
        // ===== PHASE A: scatter(prev) + gather(cur) + idx prefetch(next) =====
        #pragma unroll
        for (int k = 0; k < 4; k++) {
            int d = dPrev[k];
            if (d >= 0) {
                int e = slot + 16 * k;
                float4 ex = *(const float4*)(exA + e * 68 + js);
                float4 dl = *(const float4*)(dlP + e * 68 + js);
                float4 vv = *(const float4*)(g_v + (size_t)sPrev[k] * C + js);
                float4 nv;
                nv.x = ex.x * (vv.x + dl.x);
                nv.y = ex.y * (vv.y + dl.y);
                nv.z = ex.z * (vv.z + dl.z);
                nv.w = ex.w * (vv.w + dl.w);
                RED_V4(g_num + (size_t)d * C + js, nv);
                RED_V4(g_den + (size_t)d * C + js, ex);
            }
        }
        #pragma unroll
        for (int k = 0; k < 4; k++) {
            int e = slot + 16 * k;
            int s = seB[it * 64 + e];
            int d = deB[it * 64 + e];
            sPrev[k] = s;
            dPrev[k] = d;
            int dc = d < 0 ? 0 : d;
            // fp16 Q/K gather: one 8B load per row per thread (1 wavefront/row/group)
            uint2 qu = *(const uint2*)(g_hQ1 + (size_t)dc * C + js);
            uint2 ku = *(const uint2*)(g_hK1 + (size_t)s  * C + js);
            float4 p4d = g_pos4[dc];      // broadcast within group
            float4 p4s = g_pos4[s];
            float dpx = p4d.x - p4s.x, dpy = p4d.y - p4s.y, dpz = p4d.z - p4s.z;
            uint2 ua, up;
            if (d >= 0) {
                __half2 q0 = *(__half2*)&qu.x, q1 = *(__half2*)&qu.y;
                __half2 k0 = *(__half2*)&ku.x, k1 = *(__half2*)&ku.y;
                __half2 a0 = __hmax2(__hadd2(__hsub2(q0, k0), ba1h0), hzero);
                __half2 a1 = __hmax2(__hadd2(__hsub2(q1, k1), ba1h1), hzero);
                ua.x = *(unsigned*)&a0;
                ua.y = *(unsigned*)&a1;
                float r0p = fmaf(dpx, pwx.x, fmaf(dpy, pwy.x, fmaf(dpz, pwz.x, bp1.x)));
                float r1p = fmaf(dpx, pwx.y, fmaf(dpy, pwy.y, fmaf(dpz, pwz.y, bp1.y)));
                float r2p = fmaf(dpx, pwx.z, fmaf(dpy, pwy.z, fmaf(dpz, pwz.z, bp1.z)));
                float r3p = fmaf(dpx, pwx.w, fmaf(dpy, pwy.w, fmaf(dpz, pwz.w, bp1.w)));
                up.x = pack_h2(fmaxf(r0p, 0.f), fmaxf(r1p, 0.f));
                up.y = pack_h2(fmaxf(r2p, 0.f), fmaxf(r3p, 0.f));
            } else {
                ua = make_uint2(0u, 0u);
                up = ua;
            }
            *(uint2*)(hidA16 + e * 72 + js) = ua;
            *(uint2*)(hidP16 + e * 72 + js) = up;
        }
        {
            int ntile = tile + gridDim.x;
            if (ntile < ntiles) {
                int base = ntile << 6;
                int ib = (it ^ 1) * 64;
                if (tid < 64) {
                    int e = base + tid;
                    seB[ib + tid] = (e < E) ? src[e] : 0;
                } else if (tid < 128) {
                    int e = base + tid - 64;
                    deB[ib + tid - 64] = (e < E) ? dst[e] : -1;
                }
            }
        }
        __syncthreads();

        // ===== PHASE B: fp16 m16n8k16 MMA (ldmatrix A) + epilogue =====
        float acc[2][4][4];
        #pragma unroll
        for (int s2 = 0; s2 < 2; s2++)
            #pragma unroll
            for (int nt = 0; nt < 4; nt++) {
                acc[s2][nt][0] = bias0[nt];
                acc[s2][nt][1] = bias1[nt];
                acc[s2][nt][2] = bias0[nt];
                acc[s2][nt][3] = bias1[nt];
            }
        #pragma unroll
        for (int kt = 0; kt < 4; kt++) {
            unsigned a0[4], a1[4];
            ldsm_x4(a0[0], a0[1], a0[2], a0[3], aAddr0 + kt * 32);
            ldsm_x4(a1[0], a1[1], a1[2], a1[3], aAddr1 + kt * 32);
            #pragma unroll
            for (int nt = 0; nt < 4; nt++) {
                MMA_F16(acc[0][nt], a0, bB[kt][nt].x, bB[kt][nt].y);
                MMA_F16(acc[1][nt], a1, bB[kt][nt].x, bB[kt][nt].y);
            }
        }
        {
            int rA = lane >> 2;
            int cbv = 2 * (lane & 3);
            #pragma unroll
            for (int s2 = 0; s2 < 2; s2++) {
                int rb = (s2 ? r1m : r0m) + rA;
                #pragma unroll
                for (int nt = 0; nt < 4; nt++) {
                    int col = n0b + nt * 8 + cbv;
                    float v0, v1, v2, v3;
                    if (isA) {
                        v0 = __expf(fmaxf(acc[s2][nt][0], 0.f));
                        v1 = __expf(fmaxf(acc[s2][nt][1], 0.f));
                        v2 = __expf(fmaxf(acc[s2][nt][2], 0.f));
                        v3 = __expf(fmaxf(acc[s2][nt][3], 0.f));
                    } else {
                        v0 = fmaxf(acc[s2][nt][0], 0.f);
                        v1 = fmaxf(acc[s2][nt][1], 0.f);
                        v2 = fmaxf(acc[s2][nt][2], 0.f);
                        v3 = fmaxf(acc[s2][nt][3], 0.f);
                    }
                    *(float2*)(res + rb * 68 + col)       = make_float2(v0, v1);
                    *(float2*)(res + (rb + 8) * 68 + col) = make_float2(v2, v3);
                }
            }
        }
        __syncthreads();
    }

    // ===== pipeline drain: scatter of the final tile =====
    #pragma unroll
    for (int k = 0; k < 4; k++) {
        int d = dPrev[k];
        if (d >= 0) {
            int e = slot + 16 * k;
            float4 ex = *(const float4*)(exA + e * 68 + js);
            float4 dl = *(const float4*)(dlP + e * 68 + js);
            float4 vv = *(const float4*)(g_v + (size_t)sPrev[k] * C + js);
            float4 nv;
            nv.x = ex.x * (vv.x + dl.x);
            nv.y = ex.y * (vv.y + dl.y);
            nv.z = ex.z * (vv.z + dl.z);
            nv.w = ex.w * (vv.w + dl.w);
            RED_V4(g_num + (size_t)d * C + js, nv);
            RED_V4(g_den + (size_t)d * C + js, ex);
        }
    }
}

// ---------------- K3: out kernel — tf32 MMA over 64-node tiles ------------------
__global__ void __launch_bounds__(256)
out_kernel(const float* __restrict__ b_out, float* __restrict__ out, int n)
{
    __shared__ float rs[64 * 68];
    int tid  = threadIdx.x;
    int lane = tid & 31;
    int wid  = tid >> 5;
    int base = blockIdx.x * 64;

    for (int t = tid; t < 1024; t += 256) {
        int row = t >> 4;
        int col = (t & 15) * 4;
        int node = base + row;
        float4 r = make_float4(0.f, 0.f, 0.f, 0.f);
        if (node < n) {
            float4 nu = *(const float4*)(g_num + (size_t)node * C + col);
            float4 de = *(const float4*)(g_den + (size_t)node * C + col);
            r.x = __uint_as_float(f2tf32(nu.x / (de.x + 1e-16f)));
            r.y = __uint_as_float(f2tf32(nu.y / (de.y + 1e-16f)));
            r.z = __uint_as_float(f2tf32(nu.z / (de.z + 1e-16f)));
            r.w = __uint_as_float(f2tf32(nu.w / (de.w + 1e-16f)));
        }
        *(float4*)(rs + row * 68 + col) = r;
    }
    __syncthreads();

    int r0 = (wid & 3) * 16;
    int nh = wid >> 2;
    int n0 = nh * 32;
    int rA = lane >> 2;
    int cb = 2 * (lane & 3);
    int rowg0 = base + r0 + rA;
    int rowg1 = rowg0 + 8;

    float acc[4][4];
    #pragma unroll
    for (int nt = 0; nt < 4; nt++) {
        int col = n0 + nt * 8 + cb;
        float b0 = b_out[col], b1 = b_out[col + 1];
        acc[nt][0] = b0; acc[nt][1] = b1; acc[nt][2] = b0; acc[nt][3] = b1;
    }
    #pragma unroll
    for (int kt = 0; kt < 8; kt++) {
        int cA = kt * 8 + (lane & 3);
        unsigned a[4];
        a[0] = __float_as_uint(rs[(r0 + rA) * 68 + cA]);
        a[1] = __float_as_uint(rs[(r0 + 8 + rA) * 68 + cA]);
        a[2] = __float_as_uint(rs[(r0 + rA) * 68 + cA + 4]);
        a[3] = __float_as_uint(rs[(r0 + 8 + rA) * 68 + cA + 4]);
        #pragma unroll
        for (int nt = 0; nt < 4; nt++) {
            float2 b = ((const float2*)g_fWout)[(kt * 8 + nh * 4 + nt) * 32 + lane];
            MMA_TF32(acc[nt], a, __float_as_uint(b.x), __float_as_uint(b.y));
        }
    }
    #pragma unroll
    for (int nt = 0; nt < 4; nt++) {
        int col = n0 + nt * 8 + cb;
        if (rowg0 < n)
            *(float2*)(out + (size_t)rowg0 * C + col) =
                make_float2(fmaxf(acc[nt][0], 0.f), fmaxf(acc[nt][1], 0.f));
        if (rowg1 < n)
            *(float2*)(out + (size_t)rowg1 * C + col) =
                make_float2(fmaxf(acc[nt][2], 0.f), fmaxf(acc[nt][3], 0.f));
    }
}

// ---------------- launch --------------------------------------------------------
extern "C" void kernel_launch(void* const* d_in, const int* in_sizes, int n_in,
                              void* d_out, int out_size)
{
    const float* x      = (const float*)d_in[0];
    const float* pos    = (const float*)d_in[1];
    const int*   ei     = (const int*)  d_in[2];
    const float* W_in   = (const float*)d_in[3];
    const float* b_in   = (const float*)d_in[4];
    const float* W_out  = (const float*)d_in[5];
    const float* b_out  = (const float*)d_in[6];
    const float* W_lin  = (const float*)d_in[7];
    const float* W_src  = (const float*)d_in[8];
    const float* W_dst  = (const float*)d_in[9];
    const float* pos_w1 = (const float*)d_in[10];
    const float* pos_b1 = (const float*)d_in[11];
    const float* pos_w2 = (const float*)d_in[12];
    const float* pos_b2 = (const float*)d_in[13];
    const float* att_w1 = (const float*)d_in[14];
    const float* att_b1 = (const float*)d_in[15];
    const float* att_w2 = (const float*)d_in[16];
    const float* att_b2 = (const float*)d_in[17];

    int n = in_sizes[0] / C;
    int E = in_sizes[2] / 2;
    const int* srcArr = ei;
    const int* dstArr = ei + E;

    size_t smemNode = (size_t)(3 * 64 * 68) * sizeof(float);   // 52224
    size_t smemEdge = 54272;
    cudaFuncSetAttribute(node_kernel, cudaFuncAttributeMaxDynamicSharedMemorySize, (int)smemNode);
    cudaFuncSetAttribute(edge_kernel, cudaFuncAttributeMaxDynamicSharedMemorySize, (int)smemEdge);

    int tilesN = (n + 63) / 64;

    prep_kernel<<<1, 256>>>(att_w1, W_dst, W_src, W_in, W_lin, att_w2, pos_w2, W_out,
                            pos_b1, pos_b2);
    node_kernel<<<tilesN, 256, smemNode>>>(x, pos, b_in, att_b1, att_b2, n);
    spacer_kernel<<<1, 32>>>();   // keeps edge_kernel at launch #4 (ncu capture slot)
    edge_kernel<<<444, 256, smemEdge>>>(srcArr, dstArr, att_b1, pos_b1, pos_w1,
                                        att_b2, pos_b2, E);
    out_kernel<<<tilesN, 256>>>(b_out, (float*)d_out, n);
}

// round 13
// speedup vs baseline: 1.3624x; 1.0015x over previous
#include <cuda_runtime.h>
#include <cuda_fp16.h>
#include <cstdint>

#define C 64
#define MAXN 50000
#define MAXE 800000

// ---------------- device scratch (static: no allocation allowed) ----------------
__device__ float  g_v[MAXN * C];
__device__ __half g_hQ1[MAXN * C];
__device__ __half g_hK1[MAXN * C];
__device__ float4 g_pos4[MAXN];
__device__ float  g_num[MAXN * C];
__device__ float  g_den[MAXN * C];
__device__ float g_Mq_t[C * C];
__device__ float g_Mk_t[C * C];
__device__ float g_Win_t[C * C];
__device__ float g_Wlin_t[C * C];
__device__ float g_w2a_t[C * C];
__device__ float g_w2p_t[C * C];
__device__ float g_Wout_t[C * C];
__device__ float g_delta0[C];
__device__ float g_fWin[4096];
__device__ float g_fWlin[4096];
__device__ float g_fMq[4096];
__device__ float g_fMk[4096];
__device__ float g_fW2a[4096];
__device__ float g_fWout[4096];
// fp16 B fragments for edge MLP-2 GEMMs: [(kt*8+nt)*32+lane] -> uint2 {b0,b1}
__device__ uint2 g_hW2a[1024];
__device__ uint2 g_hW2p[1024];

__device__ __forceinline__ unsigned f2tf32(float f) {
    unsigned r;
    asm("cvt.rna.tf32.f32 %0, %1;" : "=r"(r) : "f"(f));
    return r;
}
__device__ __forceinline__ unsigned pack_h2(float a, float b) {
    __half2 h = __floats2half2_rn(a, b);
    return *reinterpret_cast<unsigned*>(&h);
}

#define MMA_TF32(d, a, b0, b1)                                               \
    asm volatile("mma.sync.aligned.m16n8k8.row.col.f32.tf32.tf32.f32 "       \
                 "{%0,%1,%2,%3}, {%4,%5,%6,%7}, {%8,%9}, {%0,%1,%2,%3};"     \
                 : "+f"(d[0]), "+f"(d[1]), "+f"(d[2]), "+f"(d[3])            \
                 : "r"(a[0]), "r"(a[1]), "r"(a[2]), "r"(a[3]),               \
                   "r"(b0), "r"(b1))

#define MMA_F16(d, a, b0, b1)                                                \
    asm volatile("mma.sync.aligned.m16n8k16.row.col.f32.f16.f16.f32 "        \
                 "{%0,%1,%2,%3}, {%4,%5,%6,%7}, {%8,%9}, {%0,%1,%2,%3};"     \
                 : "+f"(d[0]), "+f"(d[1]), "+f"(d[2]), "+f"(d[3])            \
                 : "r"(a[0]), "r"(a[1]), "r"(a[2]), "r"(a[3]),               \
                   "r"(b0), "r"(b1))

#define RED_V4(ptr, v)                                                       \
    asm volatile("red.global.add.v4.f32 [%0], {%1,%2,%3,%4};"                \
                 :: "l"(ptr), "f"((v).x), "f"((v).y), "f"((v).z), "f"((v).w) \
                 : "memory")

#define HBAR(id)                                                             \
    asm volatile("bar.sync %0, 128;" :: "r"(id) : "memory")

__device__ __forceinline__ void ldsm_x4(unsigned& r0, unsigned& r1,
                                        unsigned& r2, unsigned& r3, unsigned addr) {
    asm volatile("ldmatrix.sync.aligned.m8n8.x4.shared.b16 {%0,%1,%2,%3}, [%4];"
                 : "=r"(r0), "=r"(r1), "=r"(r2), "=r"(r3) : "r"(addr));
}

// ---------------- K0: weight prep ------------------------------------------------
__global__ void prep_kernel(const float* __restrict__ att_w1,
                            const float* __restrict__ W_dst,
                            const float* __restrict__ W_src,
                            const float* __restrict__ W_in,
                            const float* __restrict__ W_lin,
                            const float* __restrict__ att_w2,
                            const float* __restrict__ pos_w2,
                            const float* __restrict__ W_out,
                            const float* __restrict__ pos_b1,
                            const float* __restrict__ pos_b2)
{
    __shared__ float s_a[C * C];
    __shared__ float s_d[C * C];
    __shared__ float s_s[C * C];
    int tid = threadIdx.x;
    for (int t = tid; t < C * C; t += blockDim.x) {
        s_a[t] = att_w1[t];
        s_d[t] = W_dst[t];
        s_s[t] = W_src[t];
    }
    __syncthreads();
    for (int idx = tid; idx < C * C; idx += blockDim.x) {
        int t = idx >> 6, j = idx & 63;
        float aq = 0.f, ak = 0.f;
        #pragma unroll 8
        for (int u = 0; u < C; u++) {
            float a = s_a[t * C + u];
            aq = fmaf(a, s_d[u * C + j], aq);
            ak = fmaf(a, s_s[u * C + j], ak);
        }
        g_Mq_t[j * C + t] = aq;
        g_Mk_t[j * C + t] = ak;
    }
    for (int idx = tid; idx < C * C; idx += blockDim.x) {
        int cc = idx >> 6, j = idx & 63;
        g_Win_t[j * C + cc]  = W_in[idx];
        g_Wlin_t[j * C + cc] = W_lin[idx];
        g_w2a_t[j * C + cc]  = att_w2[idx];
        g_w2p_t[j * C + cc]  = pos_w2[idx];
        g_Wout_t[j * C + cc] = W_out[idx];
    }
    if (tid < C) {
        float acc = pos_b2[tid];
        #pragma unroll 8
        for (int j = 0; j < C; j++)
            acc = fmaf(fmaxf(pos_b1[j], 0.f), pos_w2[tid * C + j], acc);
        g_delta0[tid] = fmaxf(acc, 0.f);
    }
    __syncthreads();
    for (int t = tid; t < 2048; t += blockDim.x) {
        int kt   = t >> 8;
        int nt   = (t >> 5) & 7;
        int lane = t & 31;
        int kr = kt * 8 + (lane & 3);
        int nc = nt * 8 + (lane >> 2);
        int lo = kr * 64 + nc, hi = (kr + 4) * 64 + nc;
        ((float2*)g_fWin)[t]  = make_float2(__uint_as_float(f2tf32(g_Win_t[lo])),
                                            __uint_as_float(f2tf32(g_Win_t[hi])));
        ((float2*)g_fWlin)[t] = make_float2(__uint_as_float(f2tf32(g_Wlin_t[lo])),
                                            __uint_as_float(f2tf32(g_Wlin_t[hi])));
        ((float2*)g_fMq)[t]   = make_float2(__uint_as_float(f2tf32(g_Mq_t[lo])),
                                            __uint_as_float(f2tf32(g_Mq_t[hi])));
        ((float2*)g_fMk)[t]   = make_float2(__uint_as_float(f2tf32(g_Mk_t[lo])),
                                            __uint_as_float(f2tf32(g_Mk_t[hi])));
        ((float2*)g_fW2a)[t]  = make_float2(__uint_as_float(f2tf32(g_w2a_t[lo])),
                                            __uint_as_float(f2tf32(g_w2a_t[hi])));
        ((float2*)g_fWout)[t] = make_float2(__uint_as_float(f2tf32(g_Wout_t[lo])),
                                            __uint_as_float(f2tf32(g_Wout_t[hi])));
    }
    // fp16 B fragments for edge kernel (m16n8k16)
    for (int t = tid; t < 1024; t += blockDim.x) {
        int kt   = t >> 8;
        int nt   = (t >> 5) & 7;
        int lane = t & 31;
        int tig = lane & 3, gid = lane >> 2;
        int n  = nt * 8 + gid;
        int k0 = kt * 16 + tig * 2;
        uint2 ua, up;
        ua.x = pack_h2(g_w2a_t[k0 * 64 + n],       g_w2a_t[(k0 + 1) * 64 + n]);
        ua.y = pack_h2(g_w2a_t[(k0 + 8) * 64 + n], g_w2a_t[(k0 + 9) * 64 + n]);
        up.x = pack_h2(g_w2p_t[k0 * 64 + n],       g_w2p_t[(k0 + 1) * 64 + n]);
        up.y = pack_h2(g_w2p_t[(k0 + 8) * 64 + n], g_w2p_t[(k0 + 9) * 64 + n]);
        g_hW2a[t] = ua;
        g_hW2p[t] = up;
    }
}

// ---------------- dummy (instrumentation spacer so ncu window hits edge_kernel) --
__global__ void spacer_kernel() {}

// ---------------- K1: node kernel — 4 fused tf32 GEMMs over 64-node tiles -------
__global__ void __launch_bounds__(256)
node_kernel(const float* __restrict__ x,
            const float* __restrict__ pos,
            const float* __restrict__ b_in,
            const float* __restrict__ att_b1,
            const float* __restrict__ att_b2,
            int n)
{
    extern __shared__ float sm[];
    float* xs = sm;
    float* hs = sm + 4352;
    float* vs = sm + 8704;
    int tid  = threadIdx.x;
    int lane = tid & 31;
    int wid  = tid >> 5;
    int base = blockIdx.x * 64;

    for (int t = tid; t < 1024; t += 256) {
        int row = t >> 4;
        int col = (t & 15) * 4;
        int node = base + row;
        float4 v4 = make_float4(0.f, 0.f, 0.f, 0.f);
        if (node < n) v4 = *(const float4*)(x + (size_t)node * C + col);
        float4 r;
        r.x = __uint_as_float(f2tf32(v4.x));
        r.y = __uint_as_float(f2tf32(v4.y));
        r.z = __uint_as_float(f2tf32(v4.z));
        r.w = __uint_as_float(f2tf32(v4.w));
        *(float4*)(xs + row * 68 + col) = r;
    }
    if (tid < 64) {
        int node = base + tid;
        if (node < n) {
            g_pos4[node] = make_float4(pos[(size_t)node * 3 + 0],
                                       pos[(size_t)node * 3 + 1],
                                       pos[(size_t)node * 3 + 2], 0.f);
        }
    }
    __syncthreads();

    int r0 = (wid & 3) * 16;
    int nh = wid >> 2;
    int n0 = nh * 32;
    int rA = lane >> 2;
    int cb = 2 * (lane & 3);
    int rowg0 = base + r0 + rA;
    int rowg1 = rowg0 + 8;
    bool ok0 = rowg0 < n, ok1 = rowg1 < n;

    {
        float acc[4][4];
        #pragma unroll
        for (int nt = 0; nt < 4; nt++) {
            int col = n0 + nt * 8 + cb;
            float b0 = b_in[col], b1 = b_in[col + 1];
            acc[nt][0] = b0; acc[nt][1] = b1; acc[nt][2] = b0; acc[nt][3] = b1;
        }
        #pragma unroll
        for (int kt = 0; kt < 8; kt++) {
            int cA = kt * 8 + (lane & 3);
            unsigned a[4];
            a[0] = __float_as_uint(xs[(r0 + rA) * 68 + cA]);
            a[1] = __float_as_uint(xs[(r0 + 8 + rA) * 68 + cA]);
            a[2] = __float_as_uint(xs[(r0 + rA) * 68 + cA + 4]);
            a[3] = __float_as_uint(xs[(r0 + 8 + rA) * 68 + cA + 4]);
            #pragma unroll
            for (int nt = 0; nt < 4; nt++) {
                float2 b = ((const float2*)g_fWin)[(kt * 8 + nh * 4 + nt) * 32 + lane];
                MMA_TF32(acc[nt], a, __float_as_uint(b.x), __float_as_uint(b.y));
            }
        }
        #pragma unroll
        for (int nt = 0; nt < 4; nt++) {
            int col = n0 + nt * 8 + cb;
            hs[(r0 + rA) * 68 + col]       = __uint_as_float(f2tf32(fmaxf(acc[nt][0], 0.f)));
            hs[(r0 + rA) * 68 + col + 1]   = __uint_as_float(f2tf32(fmaxf(acc[nt][1], 0.f)));
            hs[(r0 + 8 + rA) * 68 + col]     = __uint_as_float(f2tf32(fmaxf(acc[nt][2], 0.f)));
            hs[(r0 + 8 + rA) * 68 + col + 1] = __uint_as_float(f2tf32(fmaxf(acc[nt][3], 0.f)));
        }
    }
    __syncthreads();

    {
        float acc[4][4];
        #pragma unroll
        for (int nt = 0; nt < 4; nt++)
            #pragma unroll
            for (int q = 0; q < 4; q++) acc[nt][q] = 0.f;
        #pragma unroll
        for (int kt = 0; kt < 8; kt++) {
            int cA = kt * 8 + (lane & 3);
            unsigned a[4];
            a[0] = __float_as_uint(hs[(r0 + rA) * 68 + cA]);
            a[1] = __float_as_uint(hs[(r0 + 8 + rA) * 68 + cA]);
            a[2] = __float_as_uint(hs[(r0 + rA) * 68 + cA + 4]);
            a[3] = __float_as_uint(hs[(r0 + 8 + rA) * 68 + cA + 4]);
            #pragma unroll
            for (int nt = 0; nt < 4; nt++) {
                float2 b = ((const float2*)g_fWlin)[(kt * 8 + nh * 4 + nt) * 32 + lane];
                MMA_TF32(acc[nt], a, __float_as_uint(b.x), __float_as_uint(b.y));
            }
        }
        #pragma unroll
        for (int nt = 0; nt < 4; nt++) {
            int col = n0 + nt * 8 + cb;
            vs[(r0 + rA) * 68 + col]         = acc[nt][0];
            vs[(r0 + rA) * 68 + col + 1]     = acc[nt][1];
            vs[(r0 + 8 + rA) * 68 + col]     = acc[nt][2];
            vs[(r0 + 8 + rA) * 68 + col + 1] = acc[nt][3];
            if (ok0) *(float2*)(g_v + (size_t)rowg0 * C + col) = make_float2(acc[nt][0], acc[nt][1]);
            if (ok1) *(float2*)(g_v + (size_t)rowg1 * C + col) = make_float2(acc[nt][2], acc[nt][3]);
        }
    }
    {
        float aq[4][4], ak[4][4];
        #pragma unroll
        for (int nt = 0; nt < 4; nt++)
            #pragma unroll
            for (int q = 0; q < 4; q++) { aq[nt][q] = 0.f; ak[nt][q] = 0.f; }
        #pragma unroll
        for (int kt = 0; kt < 8; kt++) {
            int cA = kt * 8 + (lane & 3);
            unsigned a[4];
            a[0] = __float_as_uint(hs[(r0 + rA) * 68 + cA]);
            a[1] = __float_as_uint(hs[(r0 + 8 + rA) * 68 + cA]);
            a[2] = __float_as_uint(hs[(r0 + rA) * 68 + cA + 4]);
            a[3] = __float_as_uint(hs[(r0 + 8 + rA) * 68 + cA + 4]);
            #pragma unroll
            for (int nt = 0; nt < 4; nt++) {
                float2 bq = ((const float2*)g_fMq)[(kt * 8 + nh * 4 + nt) * 32 + lane];
                float2 bk = ((const float2*)g_fMk)[(kt * 8 + nh * 4 + nt) * 32 + lane];
                MMA_TF32(aq[nt], a, __float_as_uint(bq.x), __float_as_uint(bq.y));
                MMA_TF32(ak[nt], a, __float_as_uint(bk.x), __float_as_uint(bk.y));
            }
        }
        #pragma unroll
        for (int nt = 0; nt < 4; nt++) {
            int col = n0 + nt * 8 + cb;
            float ba0 = att_b1[col], ba1 = att_b1[col + 1];
            xs[(r0 + rA) * 68 + col]       = __uint_as_float(f2tf32(fmaxf(aq[nt][0] - ak[nt][0] + ba0, 0.f)));
            xs[(r0 + rA) * 68 + col + 1]   = __uint_as_float(f2tf32(fmaxf(aq[nt][1] - ak[nt][1] + ba1, 0.f)));
            xs[(r0 + 8 + rA) * 68 + col]     = __uint_as_float(f2tf32(fmaxf(aq[nt][2] - ak[nt][2] + ba0, 0.f)));
            xs[(r0 + 8 + rA) * 68 + col + 1] = __uint_as_float(f2tf32(fmaxf(aq[nt][3] - ak[nt][3] + ba1, 0.f)));
            if (ok0) {
                *(__half2*)(g_hQ1 + (size_t)rowg0 * C + col) = __floats2half2_rn(aq[nt][0], aq[nt][1]);
                *(__half2*)(g_hK1 + (size_t)rowg0 * C + col) = __floats2half2_rn(ak[nt][0], ak[nt][1]);
            }
            if (ok1) {
                *(__half2*)(g_hQ1 + (size_t)rowg1 * C + col) = __floats2half2_rn(aq[nt][2], aq[nt][3]);
                *(__half2*)(g_hK1 + (size_t)rowg1 * C + col) = __floats2half2_rn(ak[nt][2], ak[nt][3]);
            }
        }
    }
    __syncthreads();

    {
        float acc[4][4];
        #pragma unroll
        for (int nt = 0; nt < 4; nt++) {
            int col = n0 + nt * 8 + cb;
            float b0 = att_b2[col], b1 = att_b2[col + 1];
            acc[nt][0] = b0; acc[nt][1] = b1; acc[nt][2] = b0; acc[nt][3] = b1;
        }
        #pragma unroll
        for (int kt = 0; kt < 8; kt++) {
            int cA = kt * 8 + (lane & 3);
            unsigned a[4];
            a[0] = __float_as_uint(xs[(r0 + rA) * 68 + cA]);
            a[1] = __float_as_uint(xs[(r0 + 8 + rA) * 68 + cA]);
            a[2] = __float_as_uint(xs[(r0 + rA) * 68 + cA + 4]);
            a[3] = __float_as_uint(xs[(r0 + 8 + rA) * 68 + cA + 4]);
            #pragma unroll
            for (int nt = 0; nt < 4; nt++) {
                float2 b = ((const float2*)g_fW2a)[(kt * 8 + nh * 4 + nt) * 32 + lane];
                MMA_TF32(acc[nt], a, __float_as_uint(b.x), __float_as_uint(b.y));
            }
        }
        #pragma unroll
        for (int nt = 0; nt < 4; nt++) {
            int col = n0 + nt * 8 + cb;
            float d0 = g_delta0[col], d1 = g_delta0[col + 1];
            float e0 = __expf(fmaxf(acc[nt][0], 0.f));
            float e1 = __expf(fmaxf(acc[nt][1], 0.f));
            float e2 = __expf(fmaxf(acc[nt][2], 0.f));
            float e3 = __expf(fmaxf(acc[nt][3], 0.f));
            if (ok0) {
                float v0 = vs[(r0 + rA) * 68 + col];
                float v1 = vs[(r0 + rA) * 68 + col + 1];
                *(float2*)(g_den + (size_t)rowg0 * C + col) = make_float2(e0, e1);
                *(float2*)(g_num + (size_t)rowg0 * C + col) = make_float2(e0 * (v0 + d0), e1 * (v1 + d1));
            }
            if (ok1) {
                float v2 = vs[(r0 + 8 + rA) * 68 + col];
                float v3 = vs[(r0 + 8 + rA) * 68 + col + 1];
                *(float2*)(g_den + (size_t)rowg1 * C + col) = make_float2(e2, e3);
                *(float2*)(g_num + (size_t)rowg1 * C + col) = make_float2(e2 * (v2 + d0), e3 * (v3 + d1));
            }
        }
    }
}

// ---------------- K2: edge kernel — TWO independent 128-thread half-pipelines ---
// Per-half smem (offset h*27136 bytes):
//   [0, 4608)      hidA16  32 rows x 72 halves
//   [4608, 9216)   hidP16
//   [9216, 17920)  exA     32 x 68 fp32
//   [17920, 26624) dlP
//   [26624, 26880) seB [2][32]
//   [26880, 27136) deB [2][32]
__global__ void __launch_bounds__(256, 3)
edge_kernel(const int* __restrict__ src, const int* __restrict__ dst,
            const float* __restrict__ att_b1, const float* __restrict__ pos_b1,
            const float* __restrict__ pos_w1,
            const float* __restrict__ att_b2, const float* __restrict__ pos_b2,
            int E)
{
    extern __shared__ char smE[];
    int tid  = threadIdx.x;
    int lane = tid & 31;
    int wid  = tid >> 5;
    bool isA = (wid < 4);
    int sub  = wid & 3;
    int h    = sub >> 1;               // half-pipeline id (0/1)
    int nhE  = sub & 1;
    int n0b  = nhE * 32;

    char* hb = smE + h * 27136;
    __half* hidA16 = (__half*)hb;
    __half* hidP16 = (__half*)(hb + 4608);
    float*  exA    = (float*)(hb + 9216);
    float*  dlP    = (float*)(hb + 17920);
    int*    seB    = (int*)(hb + 26624);
    int*    deB    = (int*)(hb + 26880);

    const float* b2 = isA ? att_b2 : pos_b2;
    __half* hid = isA ? hidA16 : hidP16;
    float*  res = isA ? exA    : dlP;

    // preload fp16 B fragments (reg-resident): 32 regs
    uint2 bB[4][4];
    {
        const uint2* hw2 = isA ? g_hW2a : g_hW2p;
        #pragma unroll
        for (int kt = 0; kt < 4; kt++)
            #pragma unroll
            for (int nt = 0; nt < 4; nt++)
                bB[kt][nt] = hw2[((kt * 8) + nhE * 4 + nt) * 32 + lane];
    }
    float bias0[4], bias1[4];
    #pragma unroll
    for (int nt = 0; nt < 4; nt++) {
        int col = n0b + nt * 8 + 2 * (lane & 3);
        bias0[nt] = b2[col];
        bias1[nt] = b2[col + 1];
    }

    // half-local thread id: warps {0,1,4,5}->half0, {2,3,6,7}->half1
    int hw   = (wid & 1) | ((wid >> 2) << 1);   // 0..3 within half
    int htid = hw * 32 + lane;                  // 0..127
    int hgrp = htid >> 4;                       // 8 groups of 16 lanes
    int js   = (htid & 15) << 2;                // fp32 col slice

    float4 ba1 = *(const float4*)(att_b1 + js);
    __half2 ba1h0 = __floats2half2_rn(ba1.x, ba1.y);
    __half2 ba1h1 = __floats2half2_rn(ba1.z, ba1.w);
    __half2 hzero = __floats2half2_rn(0.f, 0.f);
    float4 bp1 = *(const float4*)(pos_b1 + js);
    float4 pwx, pwy, pwz;
    {
        float3 w0 = *(const float3*)(pos_w1 + (js + 0) * 3);
        float3 w1 = *(const float3*)(pos_w1 + (js + 1) * 3);
        float3 w2 = *(const float3*)(pos_w1 + (js + 2) * 3);
        float3 w3 = *(const float3*)(pos_w1 + (js + 3) * 3);
        pwx = make_float4(w0.x, w1.x, w2.x, w3.x);
        pwy = make_float4(w0.y, w1.y, w2.y, w3.y);
        pwz = make_float4(w0.z, w1.z, w2.z, w3.z);
    }

    // ldmatrix source addresses (rows 0-15 / 16-31 of half's hid, pitch 72 halves)
    uint32_t hidBase;
    asm("{ .reg .u64 t; cvta.to.shared.u64 t, %1; cvt.u32.u64 %0, t; }"
        : "=r"(hidBase) : "l"(hid));
    uint32_t aAddr0 = hidBase + (uint32_t)((((lane & 15)) * 72 + ((lane >> 4) << 3)) * 2);
    uint32_t aAddr1 = hidBase + (uint32_t)(((16 + (lane & 15)) * 72 + ((lane >> 4) << 3)) * 2);

    int sPrev[4], dPrev[4];
    #pragma unroll
    for (int k = 0; k < 4; k++) dPrev[k] = -1;

    int nvt    = (E + 31) >> 5;               // 32-edge virtual tiles
    int H      = blockIdx.x * 2 + h;          // half-pipeline id (global)
    int stride = gridDim.x * 2;
    int barId  = h + 1;

    // prologue: prefetch first vtile's indices into buffer 0
    if (H < nvt) {
        if (htid < 32) {
            int e = (H << 5) + htid;
            seB[htid] = (e < E) ? src[e] : 0;
        } else if (htid < 64) {
            int e = (H << 5) + htid - 32;
            deB[htid - 32] = (e < E) ? dst[e] : -1;
        }
    }
    __syncthreads();   // one block-wide sync at start (covers both halves' prologue)

    int it = 0;
    for (int vt = H; vt < nvt; vt += stride, it ^= 1) {
        // ===== PHASE A: scatter(prev) + gather(cur) + idx prefetch(next) =====
        #pragma unroll
        for (int k = 0; k < 4; k++) {
            int d = dPrev[k];
            if (d >= 0) {
                int e = hgrp + 8 * k;
                float4 ex = *(const float4*)(exA + e * 68 + js);
                float4 dl = *(const float4*)(dlP + e * 68 + js);
                float4 vv = *(const float4*)(g_v + (size_t)sPrev[k] * C + js);
                float4 nv;
                nv.x = ex.x * (vv.x + dl.x);
                nv.y = ex.y * (vv.y + dl.y);
                nv.z = ex.z * (vv.z + dl.z);
                nv.w = ex.w * (vv.w + dl.w);
                RED_V4(g_num + (size_t)d * C + js, nv);
                RED_V4(g_den + (size_t)d * C + js, ex);
            }
        }
        #pragma unroll
        for (int k = 0; k < 4; k++) {
            int e = hgrp + 8 * k;       // local edge 0..31
            int s = seB[it * 32 + e];
            int d = deB[it * 32 + e];
            sPrev[k] = s;
            dPrev[k] = d;
            int dc = d < 0 ? 0 : d;
            uint2 qu = *(const uint2*)(g_hQ1 + (size_t)dc * C + js);
            uint2 ku = *(const uint2*)(g_hK1 + (size_t)s  * C + js);
            float4 p4d = g_pos4[dc];
            float4 p4s = g_pos4[s];
            float dpx = p4d.x - p4s.x, dpy = p4d.y - p4s.y, dpz = p4d.z - p4s.z;
            uint2 ua, up;
            if (d >= 0) {
                __half2 q0 = *(__half2*)&qu.x, q1 = *(__half2*)&qu.y;
                __half2 k0 = *(__half2*)&ku.x, k1 = *(__half2*)&ku.y;
                __half2 a0 = __hmax2(__hadd2(__hsub2(q0, k0), ba1h0), hzero);
                __half2 a1 = __hmax2(__hadd2(__hsub2(q1, k1), ba1h1), hzero);
                ua.x = *(unsigned*)&a0;
                ua.y = *(unsigned*)&a1;
                float r0p = fmaf(dpx, pwx.x, fmaf(dpy, pwy.x, fmaf(dpz, pwz.x, bp1.x)));
                float r1p = fmaf(dpx, pwx.y, fmaf(dpy, pwy.y, fmaf(dpz, pwz.y, bp1.y)));
                float r2p = fmaf(dpx, pwx.z, fmaf(dpy, pwy.z, fmaf(dpz, pwz.z, bp1.z)));
                float r3p = fmaf(dpx, pwx.w, fmaf(dpy, pwy.w, fmaf(dpz, pwz.w, bp1.w)));
                up.x = pack_h2(fmaxf(r0p, 0.f), fmaxf(r1p, 0.f));
                up.y = pack_h2(fmaxf(r2p, 0.f), fmaxf(r3p, 0.f));
            } else {
                ua = make_uint2(0u, 0u);
                up = ua;
            }
            *(uint2*)(hidA16 + e * 72 + js) = ua;
            *(uint2*)(hidP16 + e * 72 + js) = up;
        }
        {
            int nv2 = vt + stride;
            if (nv2 < nvt) {
                int ib = (it ^ 1) * 32;
                if (htid < 32) {
                    int e = (nv2 << 5) + htid;
                    seB[ib + htid] = (e < E) ? src[e] : 0;
                } else if (htid < 64) {
                    int e = (nv2 << 5) + htid - 32;
                    deB[ib + htid - 32] = (e < E) ? dst[e] : -1;
                }
            }
        }
        HBAR(barId);

        // ===== PHASE B: fp16 m16n8k16 MMA (ldmatrix A) + epilogue =====
        float acc[2][4][4];
        #pragma unroll
        for (int s2 = 0; s2 < 2; s2++)
            #pragma unroll
            for (int nt = 0; nt < 4; nt++) {
                acc[s2][nt][0] = bias0[nt];
                acc[s2][nt][1] = bias1[nt];
                acc[s2][nt][2] = bias0[nt];
                acc[s2][nt][3] = bias1[nt];
            }
        #pragma unroll
        for (int kt = 0; kt < 4; kt++) {
            unsigned a0[4], a1[4];
            ldsm_x4(a0[0], a0[1], a0[2], a0[3], aAddr0 + kt * 32);
            ldsm_x4(a1[0], a1[1], a1[2], a1[3], aAddr1 + kt * 32);
            #pragma unroll
            for (int nt = 0; nt < 4; nt++) {
                MMA_F16(acc[0][nt], a0, bB[kt][nt].x, bB[kt][nt].y);
                MMA_F16(acc[1][nt], a1, bB[kt][nt].x, bB[kt][nt].y);
            }
        }
        {
            int rA = lane >> 2;
            int cbv = 2 * (lane & 3);
            #pragma unroll
            for (int s2 = 0; s2 < 2; s2++) {
                int rb = s2 * 16 + rA;
                #pragma unroll
                for (int nt = 0; nt < 4; nt++) {
                    int col = n0b + nt * 8 + cbv;
                    float v0, v1, v2, v3;
                    if (isA) {
                        v0 = __expf(fmaxf(acc[s2][nt][0], 0.f));
                        v1 = __expf(fmaxf(acc[s2][nt][1], 0.f));
                        v2 = __expf(fmaxf(acc[s2][nt][2], 0.f));
                        v3 = __expf(fmaxf(acc[s2][nt][3], 0.f));
                    } else {
                        v0 = fmaxf(acc[s2][nt][0], 0.f);
                        v1 = fmaxf(acc[s2][nt][1], 0.f);
                        v2 = fmaxf(acc[s2][nt][2], 0.f);
                        v3 = fmaxf(acc[s2][nt][3], 0.f);
                    }
                    *(float2*)(res + rb * 68 + col)       = make_float2(v0, v1);
                    *(float2*)(res + (rb + 8) * 68 + col) = make_float2(v2, v3);
                }
            }
        }
        HBAR(barId);
    }

    // ===== pipeline drain: scatter of the final vtile =====
    #pragma unroll
    for (int k = 0; k < 4; k++) {
        int d = dPrev[k];
        if (d >= 0) {
            int e = hgrp + 8 * k;
            float4 ex = *(const float4*)(exA + e * 68 + js);
            float4 dl = *(const float4*)(dlP + e * 68 + js);
            float4 vv = *(const float4*)(g_v + (size_t)sPrev[k] * C + js);
            float4 nv;
            nv.x = ex.x * (vv.x + dl.x);
            nv.y = ex.y * (vv.y + dl.y);
            nv.z = ex.z * (vv.z + dl.z);
            nv.w = ex.w * (vv.w + dl.w);
            RED_V4(g_num + (size_t)d * C + js, nv);
            RED_V4(g_den + (size_t)d * C + js, ex);
        }
    }
}

// ---------------- K3: out kernel — tf32 MMA over 64-node tiles ------------------
__global__ void __launch_bounds__(256)
out_kernel(const float* __restrict__ b_out, float* __restrict__ out, int n)
{
    __shared__ float rs[64 * 68];
    int tid  = threadIdx.x;
    int lane = tid & 31;
    int wid  = tid >> 5;
    int base = blockIdx.x * 64;

    for (int t = tid; t < 1024; t += 256) {
        int row = t >> 4;
        int col = (t & 15) * 4;
        int node = base + row;
        float4 r = make_float4(0.f, 0.f, 0.f, 0.f);
        if (node < n) {
            float4 nu = *(const float4*)(g_num + (size_t)node * C + col);
            float4 de = *(const float4*)(g_den + (size_t)node * C + col);
            r.x = __uint_as_float(f2tf32(nu.x / (de.x + 1e-16f)));
            r.y = __uint_as_float(f2tf32(nu.y / (de.y + 1e-16f)));
            r.z = __uint_as_float(f2tf32(nu.z / (de.z + 1e-16f)));
            r.w = __uint_as_float(f2tf32(nu.w / (de.w + 1e-16f)));
        }
        *(float4*)(rs + row * 68 + col) = r;
    }
    __syncthreads();

    int r0 = (wid & 3) * 16;
    int nh = wid >> 2;
    int n0 = nh * 32;
    int rA = lane >> 2;
    int cb = 2 * (lane & 3);
    int rowg0 = base + r0 + rA;
    int rowg1 = rowg0 + 8;

    float acc[4][4];
    #pragma unroll
    for (int nt = 0; nt < 4; nt++) {
        int col = n0 + nt * 8 + cb;
        float b0 = b_out[col], b1 = b_out[col + 1];
        acc[nt][0] = b0; acc[nt][1] = b1; acc[nt][2] = b0; acc[nt][3] = b1;
    }
    #pragma unroll
    for (int kt = 0; kt < 8; kt++) {
        int cA = kt * 8 + (lane & 3);
        unsigned a[4];
        a[0] = __float_as_uint(rs[(r0 + rA) * 68 + cA]);
        a[1] = __float_as_uint(rs[(r0 + 8 + rA) * 68 + cA]);
        a[2] = __float_as_uint(rs[(r0 + rA) * 68 + cA + 4]);
        a[3] = __float_as_uint(rs[(r0 + 8 + rA) * 68 + cA + 4]);
        #pragma unroll
        for (int nt = 0; nt < 4; nt++) {
            float2 b = ((const float2*)g_fWout)[(kt * 8 + nh * 4 + nt) * 32 + lane];
            MMA_TF32(acc[nt], a, __float_as_uint(b.x), __float_as_uint(b.y));
        }
    }
    #pragma unroll
    for (int nt = 0; nt < 4; nt++) {
        int col = n0 + nt * 8 + cb;
        if (rowg0 < n)
            *(float2*)(out + (size_t)rowg0 * C + col) =
                make_float2(fmaxf(acc[nt][0], 0.f), fmaxf(acc[nt][1], 0.f));
        if (rowg1 < n)
            *(float2*)(out + (size_t)rowg1 * C + col) =
                make_float2(fmaxf(acc[nt][2], 0.f), fmaxf(acc[nt][3], 0.f));
    }
}

// ---------------- launch --------------------------------------------------------
extern "C" void kernel_launch(void* const* d_in, const int* in_sizes, int n_in,
                              void* d_out, int out_size)
{
    const float* x      = (const float*)d_in[0];
    const float* pos    = (const float*)d_in[1];
    const int*   ei     = (const int*)  d_in[2];
    const float* W_in   = (const float*)d_in[3];
    const float* b_in   = (const float*)d_in[4];
    const float* W_out  = (const float*)d_in[5];
    const float* b_out  = (const float*)d_in[6];
    const float* W_lin  = (const float*)d_in[7];
    const float* W_src  = (const float*)d_in[8];
    const float* W_dst  = (const float*)d_in[9];
    const float* pos_w1 = (const float*)d_in[10];
    const float* pos_b1 = (const float*)d_in[11];
    const float* pos_w2 = (const float*)d_in[12];
    const float* pos_b2 = (const float*)d_in[13];
    const float* att_w1 = (const float*)d_in[14];
    const float* att_b1 = (const float*)d_in[15];
    const float* att_w2 = (const float*)d_in[16];
    const float* att_b2 = (const float*)d_in[17];

    int n = in_sizes[0] / C;
    int E = in_sizes[2] / 2;
    const int* srcArr = ei;
    const int* dstArr = ei + E;

    size_t smemNode = (size_t)(3 * 64 * 68) * sizeof(float);   // 52224
    size_t smemEdge = 54272;                                   // 2 x 27136
    cudaFuncSetAttribute(node_kernel, cudaFuncAttributeMaxDynamicSharedMemorySize, (int)smemNode);
    cudaFuncSetAttribute(edge_kernel, cudaFuncAttributeMaxDynamicSharedMemorySize, (int)smemEdge);

    int tilesN = (n + 63) / 64;

    prep_kernel<<<1, 256>>>(att_w1, W_dst, W_src, W_in, W_lin, att_w2, pos_w2, W_out,
                            pos_b1, pos_b2);
    node_kernel<<<tilesN, 256, smemNode>>>(x, pos, b_in, att_b1, att_b2, n);
    spacer_kernel<<<1, 32>>>();   // keeps edge_kernel at launch #4 (ncu capture slot)
    edge_kernel<<<444, 256, smemEdge>>>(srcArr, dstArr, att_b1, pos_b1, pos_w1,
                                        att_b2, pos_b2, E);
    out_kernel<<<tilesN, 256>>>(b_out, (float*)d_out, n);
}